// round 4
// baseline (speedup 1.0000x reference)
#include <cuda_runtime.h>
#include <cuda_bf16.h>

#define N_NODES 100000
#define D 128
#define E_EDGES 1600000
#define SCAN_THREADS 1024
#define SCAN_CHUNK ((N_NODES + SCAN_THREADS - 1) / SCAN_THREADS)  // 98

// Scratch (device globals; no runtime allocation allowed)
__device__ float g_h[N_NODES * D];     // post-GEMM features
__device__ float g_tmp[N_NODES * D];   // layer output / next layer input
__device__ float g_dinv[N_NODES];
__device__ int   g_cnt[N_NODES];       // in-degree (without self loop)
__device__ int   g_rowptr[N_NODES + 1];
__device__ int   g_cursor[N_NODES];
__device__ int   g_csr_src[E_EDGES];

// ---------------------------------------------------------------------------
// CSR build: histogram -> scan -> scatter
// ---------------------------------------------------------------------------
__global__ void k_zero_cnt() {
    int i = blockIdx.x * blockDim.x + threadIdx.x;
    if (i < N_NODES) g_cnt[i] = 0;
}

__global__ void k_count(const int* __restrict__ ei) {
    int e = blockIdx.x * blockDim.x + threadIdx.x;
    if (e < E_EDGES) {
        int dst = ei[E_EDGES + e];
        atomicAdd(&g_cnt[dst], 1);
    }
}

__global__ void k_dinv() {
    int i = blockIdx.x * blockDim.x + threadIdx.x;
    if (i < N_NODES) g_dinv[i] = rsqrtf((float)g_cnt[i] + 1.0f);  // +1 self loop
}

// Single-block exclusive scan of g_cnt -> g_rowptr / g_cursor.
__global__ void __launch_bounds__(SCAN_THREADS)
k_scan() {
    __shared__ int part[SCAN_THREADS];
    int t = threadIdx.x;
    int beg = t * SCAN_CHUNK;
    int end = beg + SCAN_CHUNK;
    if (end > N_NODES) end = N_NODES;

    int s = 0;
    for (int i = beg; i < end; ++i) s += g_cnt[i];
    part[t] = s;
    __syncthreads();

    // Hillis-Steele inclusive scan over 1024 partials
    for (int off = 1; off < SCAN_THREADS; off <<= 1) {
        int v = (t >= off) ? part[t - off] : 0;
        __syncthreads();
        part[t] += v;
        __syncthreads();
    }
    int base = (t == 0) ? 0 : part[t - 1];

    int run = base;
    for (int i = beg; i < end; ++i) {
        g_rowptr[i] = run;
        g_cursor[i] = run;
        run += g_cnt[i];
    }
    if (t == 0) g_rowptr[N_NODES] = E_EDGES;
}

__global__ void k_scatter(const int* __restrict__ ei) {
    int e = blockIdx.x * blockDim.x + threadIdx.x;
    if (e < E_EDGES) {
        int src = ei[e];
        int dst = ei[E_EDGES + e];
        int pos = atomicAdd(&g_cursor[dst], 1);
        g_csr_src[pos] = src;
    }
}

// ---------------------------------------------------------------------------
// GEMM: g_h = SRC @ W.  Block = 64 rows x 128 cols, 256 threads, 4x8/thread.
// K processed in 4 chunks of 32 -> static smem only (16KB W + 9KB X < 48KB).
// FROM_TMP selects input: false -> X param (layer 1), true -> g_tmp.
// ---------------------------------------------------------------------------
template <bool FROM_TMP>
__global__ void __launch_bounds__(256, 2)
k_gemm(const float* __restrict__ X, const float* __restrict__ W) {
    __shared__ float Ws[32 * 128];   // K-chunk x N
    __shared__ float Xs[64 * 36];    // M-tile x K-chunk (stride 36: 144B, 16B-aligned)

    const float* src = FROM_TMP ? (const float*)g_tmp : X;
    int tid = threadIdx.x;
    int m0 = blockIdx.x * 64;

    int cg = (tid & 15) * 8;   // col base (0..120)
    int rg = (tid >> 4) * 4;   // row base (0..60)

    float acc[4][8];
#pragma unroll
    for (int i = 0; i < 4; ++i)
#pragma unroll
        for (int j = 0; j < 8; ++j) acc[i][j] = 0.0f;

    const float4* Wv = (const float4*)W;
    const float4* Xv = (const float4*)src;

#pragma unroll
    for (int kc = 0; kc < 4; ++kc) {
        // Load W chunk: rows [kc*32, kc*32+32) x 128 cols = 1024 float4
        float4* Wsv = (float4*)Ws;
#pragma unroll
        for (int i = 0; i < 4; ++i)
            Wsv[tid + i * 256] = Wv[kc * 1024 + tid + i * 256];

        // Load X chunk: 64 rows x 8 float4 = 512 float4
#pragma unroll
        for (int i = 0; i < 2; ++i) {
            int idx = tid + i * 256;
            int r = idx >> 3;       // 0..63
            int c = idx & 7;        // 0..7
            int m = m0 + r;
            float4 v = (m < N_NODES) ? Xv[m * 32 + kc * 8 + c]
                                     : make_float4(0.f, 0.f, 0.f, 0.f);
            *(float4*)&Xs[r * 36 + c * 4] = v;
        }
        __syncthreads();

#pragma unroll
        for (int k = 0; k < 32; ++k) {
            float4 w0 = *(float4*)&Ws[k * 128 + cg];
            float4 w1 = *(float4*)&Ws[k * 128 + cg + 4];
            float xr[4];
#pragma unroll
            for (int i = 0; i < 4; ++i) xr[i] = Xs[(rg + i) * 36 + k];
#pragma unroll
            for (int i = 0; i < 4; ++i) {
                acc[i][0] = fmaf(xr[i], w0.x, acc[i][0]);
                acc[i][1] = fmaf(xr[i], w0.y, acc[i][1]);
                acc[i][2] = fmaf(xr[i], w0.z, acc[i][2]);
                acc[i][3] = fmaf(xr[i], w0.w, acc[i][3]);
                acc[i][4] = fmaf(xr[i], w1.x, acc[i][4]);
                acc[i][5] = fmaf(xr[i], w1.y, acc[i][5]);
                acc[i][6] = fmaf(xr[i], w1.z, acc[i][6]);
                acc[i][7] = fmaf(xr[i], w1.w, acc[i][7]);
            }
        }
        __syncthreads();
    }

#pragma unroll
    for (int i = 0; i < 4; ++i) {
        int m = m0 + rg + i;
        if (m >= N_NODES) continue;
        ((float4*)g_h)[m * 32 + (cg >> 2)] =
            make_float4(acc[i][0], acc[i][1], acc[i][2], acc[i][3]);
        ((float4*)g_h)[m * 32 + (cg >> 2) + 1] =
            make_float4(acc[i][4], acc[i][5], acc[i][6], acc[i][7]);
    }
}

// ---------------------------------------------------------------------------
// Aggregation: one warp per dst node, lane owns one float4 of the feature.
// DST[dst] = relu( dinv[dst]*( sum_{src} dinv[src]*g_h[src]
//                              + dinv[dst]*g_h[dst] ) + b )
// No atomics: each warp exclusively owns its dst row.
// TO_OUT selects output: false -> g_tmp (layers 1,2), true -> OUT (layer 3).
// ---------------------------------------------------------------------------
template <bool TO_OUT>
__global__ void __launch_bounds__(256)
k_agg(const float* __restrict__ b, float* __restrict__ OUT) {
    int node = blockIdx.x * 8 + (threadIdx.x >> 5);
    int lane = threadIdx.x & 31;
    if (node >= N_NODES) return;

    float* dst_buf = TO_OUT ? OUT : (float*)g_tmp;
    const float4* Hv = (const float4*)g_h;

    float dv = g_dinv[node];
    float4 acc = Hv[node * 32 + lane];
    acc.x *= dv; acc.y *= dv; acc.z *= dv; acc.w *= dv;  // self-loop term

    int j = g_rowptr[node];
    int end = g_rowptr[node + 1];

    for (; j + 1 < end; j += 2) {
        int s0 = g_csr_src[j];
        int s1 = g_csr_src[j + 1];
        float n0 = g_dinv[s0];
        float n1 = g_dinv[s1];
        float4 h0 = Hv[s0 * 32 + lane];
        float4 h1 = Hv[s1 * 32 + lane];
        acc.x = fmaf(n0, h0.x, acc.x); acc.y = fmaf(n0, h0.y, acc.y);
        acc.z = fmaf(n0, h0.z, acc.z); acc.w = fmaf(n0, h0.w, acc.w);
        acc.x = fmaf(n1, h1.x, acc.x); acc.y = fmaf(n1, h1.y, acc.y);
        acc.z = fmaf(n1, h1.z, acc.z); acc.w = fmaf(n1, h1.w, acc.w);
    }
    if (j < end) {
        int s0 = g_csr_src[j];
        float n0 = g_dinv[s0];
        float4 h0 = Hv[s0 * 32 + lane];
        acc.x = fmaf(n0, h0.x, acc.x); acc.y = fmaf(n0, h0.y, acc.y);
        acc.z = fmaf(n0, h0.z, acc.z); acc.w = fmaf(n0, h0.w, acc.w);
    }

    float4 bb = *(const float4*)&b[lane * 4];
    acc.x = fmaxf(fmaf(dv, acc.x, bb.x), 0.f);
    acc.y = fmaxf(fmaf(dv, acc.y, bb.y), 0.f);
    acc.z = fmaxf(fmaf(dv, acc.z, bb.z), 0.f);
    acc.w = fmaxf(fmaf(dv, acc.w, bb.w), 0.f);
    ((float4*)dst_buf)[node * 32 + lane] = acc;
}

// ---------------------------------------------------------------------------
extern "C" void kernel_launch(void* const* d_in, const int* in_sizes, int n_in,
                              void* d_out, int out_size) {
    const float* x  = (const float*)d_in[0];
    const int*   ei = (const int*)d_in[1];   // edge_index is int32 (JAX default)
    const float* W1 = (const float*)d_in[2];
    const float* b1 = (const float*)d_in[3];
    const float* W2 = (const float*)d_in[4];
    const float* b2 = (const float*)d_in[5];
    const float* W3 = (const float*)d_in[6];
    const float* b3 = (const float*)d_in[7];
    float* out = (float*)d_out;

    // CSR build
    k_zero_cnt<<<(N_NODES + 255) / 256, 256>>>();
    k_count<<<(E_EDGES + 255) / 256, 256>>>(ei);
    k_dinv<<<(N_NODES + 255) / 256, 256>>>();
    k_scan<<<1, SCAN_THREADS>>>();
    k_scatter<<<(E_EDGES + 255) / 256, 256>>>(ei);

    const int gemm_blocks = (N_NODES + 63) / 64;
    const int agg_blocks  = (N_NODES + 7) / 8;

    // Layer 1: x -> g_h -> g_tmp
    k_gemm<false><<<gemm_blocks, 256>>>(x, W1);
    k_agg<false><<<agg_blocks, 256>>>(b1, nullptr);
    // Layer 2: g_tmp -> g_h -> g_tmp
    k_gemm<true><<<gemm_blocks, 256>>>(nullptr, W2);
    k_agg<false><<<agg_blocks, 256>>>(b2, nullptr);
    // Layer 3: g_tmp -> g_h -> out
    k_gemm<true><<<gemm_blocks, 256>>>(nullptr, W3);
    k_agg<true><<<agg_blocks, 256>>>(b3, out);
}

// round 5
// speedup vs baseline: 1.2693x; 1.2693x over previous
#include <cuda_runtime.h>
#include <cuda_bf16.h>

#define N_NODES 100000
#define D 128
#define E_EDGES 1600000
#define SCAN_BLOCKS ((N_NODES + 1023) / 1024)   // 98

// Scratch (device globals; no runtime allocation allowed)
__device__ float g_h[N_NODES * D];     // post-GEMM features
__device__ float g_tmp[N_NODES * D];   // layer output / next layer input
__device__ float g_dinv[N_NODES];
__device__ int   g_cnt[N_NODES];       // in-degree (without self loop)
__device__ int   g_rowptr[N_NODES + 1];
__device__ int   g_cursor[N_NODES];
__device__ int   g_csr_src[E_EDGES];
__device__ int   g_bsum[SCAN_BLOCKS];
__device__ int   g_boff[SCAN_BLOCKS];

// ---------------------------------------------------------------------------
// CSR build: histogram -> parallel scan -> scatter
// ---------------------------------------------------------------------------
__global__ void k_zero_cnt() {
    int i = blockIdx.x * blockDim.x + threadIdx.x;
    if (i < N_NODES) g_cnt[i] = 0;
}

__global__ void k_count(const int* __restrict__ ei) {
    int e = blockIdx.x * blockDim.x + threadIdx.x;
    if (e < E_EDGES) atomicAdd(&g_cnt[ei[E_EDGES + e]], 1);
}

// Per-block inclusive scan of 1024 counts; writes local exclusive prefix and
// per-block total.
__global__ void __launch_bounds__(1024) k_scan_a() {
    __shared__ int sm[1024];
    int t = threadIdx.x;
    int i = blockIdx.x * 1024 + t;
    int v = (i < N_NODES) ? g_cnt[i] : 0;
    sm[t] = v;
    __syncthreads();
#pragma unroll
    for (int off = 1; off < 1024; off <<= 1) {
        int u = (t >= off) ? sm[t - off] : 0;
        __syncthreads();
        sm[t] += u;
        __syncthreads();
    }
    if (i < N_NODES) g_rowptr[i] = sm[t] - v;   // local exclusive
    if (t == 1023) g_bsum[blockIdx.x] = sm[1023];
}

// Scan the 98 block sums (1 block, 128 threads).
__global__ void __launch_bounds__(128) k_scan_b() {
    __shared__ int sm[128];
    int t = threadIdx.x;
    int v = (t < SCAN_BLOCKS) ? g_bsum[t] : 0;
    sm[t] = v;
    __syncthreads();
#pragma unroll
    for (int off = 1; off < 128; off <<= 1) {
        int u = (t >= off) ? sm[t - off] : 0;
        __syncthreads();
        sm[t] += u;
        __syncthreads();
    }
    if (t < SCAN_BLOCKS) g_boff[t] = sm[t] - v;  // exclusive
}

// Add block offsets, init cursor, fuse dinv computation.
__global__ void __launch_bounds__(1024) k_scan_c() {
    int i = blockIdx.x * 1024 + threadIdx.x;
    if (i < N_NODES) {
        int r = g_rowptr[i] + g_boff[blockIdx.x];
        g_rowptr[i] = r;
        g_cursor[i] = r;
        g_dinv[i] = rsqrtf((float)g_cnt[i] + 1.0f);  // +1 self loop
    }
    if (i == 0) g_rowptr[N_NODES] = E_EDGES;
}

__global__ void k_scatter(const int* __restrict__ ei) {
    int e = blockIdx.x * blockDim.x + threadIdx.x;
    if (e < E_EDGES) {
        int src = ei[e];
        int dst = ei[E_EDGES + e];
        int pos = atomicAdd(&g_cursor[dst], 1);
        g_csr_src[pos] = src;
    }
}

// ---------------------------------------------------------------------------
// GEMM: g_h = SRC @ W.  Block = 64 rows x 128 cols, 256 threads, 4x8/thread.
// K processed in 4 chunks of 32 -> static smem only (16KB W + 9KB X < 48KB).
// ---------------------------------------------------------------------------
template <bool FROM_TMP>
__global__ void __launch_bounds__(256, 2)
k_gemm(const float* __restrict__ X, const float* __restrict__ W) {
    __shared__ float Ws[32 * 128];
    __shared__ float Xs[64 * 36];

    const float* src = FROM_TMP ? (const float*)g_tmp : X;
    int tid = threadIdx.x;
    int m0 = blockIdx.x * 64;

    int cg = (tid & 15) * 8;
    int rg = (tid >> 4) * 4;

    float acc[4][8];
#pragma unroll
    for (int i = 0; i < 4; ++i)
#pragma unroll
        for (int j = 0; j < 8; ++j) acc[i][j] = 0.0f;

    const float4* Wv = (const float4*)W;
    const float4* Xv = (const float4*)src;

#pragma unroll
    for (int kc = 0; kc < 4; ++kc) {
        float4* Wsv = (float4*)Ws;
#pragma unroll
        for (int i = 0; i < 4; ++i)
            Wsv[tid + i * 256] = Wv[kc * 1024 + tid + i * 256];

#pragma unroll
        for (int i = 0; i < 2; ++i) {
            int idx = tid + i * 256;
            int r = idx >> 3;
            int c = idx & 7;
            int m = m0 + r;
            float4 v = (m < N_NODES) ? Xv[m * 32 + kc * 8 + c]
                                     : make_float4(0.f, 0.f, 0.f, 0.f);
            *(float4*)&Xs[r * 36 + c * 4] = v;
        }
        __syncthreads();

#pragma unroll
        for (int k = 0; k < 32; ++k) {
            float4 w0 = *(float4*)&Ws[k * 128 + cg];
            float4 w1 = *(float4*)&Ws[k * 128 + cg + 4];
            float xr[4];
#pragma unroll
            for (int i = 0; i < 4; ++i) xr[i] = Xs[(rg + i) * 36 + k];
#pragma unroll
            for (int i = 0; i < 4; ++i) {
                acc[i][0] = fmaf(xr[i], w0.x, acc[i][0]);
                acc[i][1] = fmaf(xr[i], w0.y, acc[i][1]);
                acc[i][2] = fmaf(xr[i], w0.z, acc[i][2]);
                acc[i][3] = fmaf(xr[i], w0.w, acc[i][3]);
                acc[i][4] = fmaf(xr[i], w1.x, acc[i][4]);
                acc[i][5] = fmaf(xr[i], w1.y, acc[i][5]);
                acc[i][6] = fmaf(xr[i], w1.z, acc[i][6]);
                acc[i][7] = fmaf(xr[i], w1.w, acc[i][7]);
            }
        }
        __syncthreads();
    }

#pragma unroll
    for (int i = 0; i < 4; ++i) {
        int m = m0 + rg + i;
        if (m >= N_NODES) continue;
        ((float4*)g_h)[m * 32 + (cg >> 2)] =
            make_float4(acc[i][0], acc[i][1], acc[i][2], acc[i][3]);
        ((float4*)g_h)[m * 32 + (cg >> 2) + 1] =
            make_float4(acc[i][4], acc[i][5], acc[i][6], acc[i][7]);
    }
}

// ---------------------------------------------------------------------------
// Aggregation: one warp per dst node, lane owns one float4 of the feature.
// Indices + norms loaded coalesced 32-at-a-time by lanes, broadcast via shfl,
// inner gather unrolled 4-wide for MLP.
// ---------------------------------------------------------------------------
template <bool TO_OUT>
__global__ void __launch_bounds__(256)
k_agg(const float* __restrict__ b, float* __restrict__ OUT) {
    int node = blockIdx.x * 8 + (threadIdx.x >> 5);
    int lane = threadIdx.x & 31;
    if (node >= N_NODES) return;

    float* dst_buf = TO_OUT ? OUT : (float*)g_tmp;
    const float4* Hv = (const float4*)g_h;

    float dv = g_dinv[node];
    float4 acc = Hv[node * 32 + lane];
    acc.x *= dv; acc.y *= dv; acc.z *= dv; acc.w *= dv;  // self-loop term

    int j = g_rowptr[node];
    int end = g_rowptr[node + 1];

    while (j < end) {
        int take = end - j;
        if (take > 32) take = 32;
        int   sidx = 0;
        float snrm = 0.0f;
        if (lane < take) {
            sidx = g_csr_src[j + lane];
            snrm = g_dinv[sidx];
        }
#pragma unroll 4
        for (int t = 0; t < take; ++t) {
            int   s = __shfl_sync(0xffffffffu, sidx, t);
            float n = __shfl_sync(0xffffffffu, snrm, t);
            float4 h = Hv[s * 32 + lane];
            acc.x = fmaf(n, h.x, acc.x);
            acc.y = fmaf(n, h.y, acc.y);
            acc.z = fmaf(n, h.z, acc.z);
            acc.w = fmaf(n, h.w, acc.w);
        }
        j += take;
    }

    float4 bb = *(const float4*)&b[lane * 4];
    acc.x = fmaxf(fmaf(dv, acc.x, bb.x), 0.f);
    acc.y = fmaxf(fmaf(dv, acc.y, bb.y), 0.f);
    acc.z = fmaxf(fmaf(dv, acc.z, bb.z), 0.f);
    acc.w = fmaxf(fmaf(dv, acc.w, bb.w), 0.f);
    ((float4*)dst_buf)[node * 32 + lane] = acc;
}

// ---------------------------------------------------------------------------
extern "C" void kernel_launch(void* const* d_in, const int* in_sizes, int n_in,
                              void* d_out, int out_size) {
    const float* x  = (const float*)d_in[0];
    const int*   ei = (const int*)d_in[1];   // edge_index is int32
    const float* W1 = (const float*)d_in[2];
    const float* b1 = (const float*)d_in[3];
    const float* W2 = (const float*)d_in[4];
    const float* b2 = (const float*)d_in[5];
    const float* W3 = (const float*)d_in[6];
    const float* b3 = (const float*)d_in[7];
    float* out = (float*)d_out;

    // CSR build
    k_zero_cnt<<<(N_NODES + 255) / 256, 256>>>();
    k_count<<<(E_EDGES + 255) / 256, 256>>>(ei);
    k_scan_a<<<SCAN_BLOCKS, 1024>>>();
    k_scan_b<<<1, 128>>>();
    k_scan_c<<<SCAN_BLOCKS, 1024>>>();
    k_scatter<<<(E_EDGES + 255) / 256, 256>>>(ei);

    const int gemm_blocks = (N_NODES + 63) / 64;
    const int agg_blocks  = (N_NODES + 7) / 8;

    // Layer 1: x -> g_h -> g_tmp
    k_gemm<false><<<gemm_blocks, 256>>>(x, W1);
    k_agg<false><<<agg_blocks, 256>>>(b1, nullptr);
    // Layer 2: g_tmp -> g_h -> g_tmp
    k_gemm<true><<<gemm_blocks, 256>>>(nullptr, W2);
    k_agg<false><<<agg_blocks, 256>>>(b2, nullptr);
    // Layer 3: g_tmp -> g_h -> out
    k_gemm<true><<<gemm_blocks, 256>>>(nullptr, W3);
    k_agg<true><<<agg_blocks, 256>>>(b3, out);
}

// round 7
// speedup vs baseline: 1.5067x; 1.1870x over previous
#include <cuda_runtime.h>
#include <cuda_bf16.h>

#define N_NODES 100000
#define D 128
#define E_EDGES 1600000
#define SCAN_BLOCKS ((N_NODES + 1023) / 1024)   // 98

// Scratch (device globals; no runtime allocation allowed)
__device__ float g_h[N_NODES * D];     // post-GEMM features
__device__ float g_tmp[N_NODES * D];   // layer output / next layer input
__device__ float g_dinv[N_NODES];
__device__ int   g_cnt[N_NODES];
__device__ int   g_rowptr[N_NODES + 1];
__device__ int   g_cursor[N_NODES];
__device__ int   g_csr_src[E_EDGES];
__device__ int   g_bsum[SCAN_BLOCKS];
__device__ int   g_boff[SCAN_BLOCKS];
__device__ __nv_bfloat16 g_wm[D * D];  // W^T main bf16, [n][k] (k contiguous)
__device__ __nv_bfloat16 g_wr[D * D];  // W^T residual bf16

// ---------------------------------------------------------------------------
// Helpers
// ---------------------------------------------------------------------------
__device__ __forceinline__ void split2(float2 v, unsigned& m, unsigned& r) {
    __nv_bfloat16 mx = __float2bfloat16_rn(v.x);
    __nv_bfloat16 my = __float2bfloat16_rn(v.y);
    __nv_bfloat16 rx = __float2bfloat16_rn(v.x - __bfloat162float(mx));
    __nv_bfloat16 ry = __float2bfloat16_rn(v.y - __bfloat162float(my));
    m = (unsigned)__bfloat16_as_ushort(mx) | ((unsigned)__bfloat16_as_ushort(my) << 16);
    r = (unsigned)__bfloat16_as_ushort(rx) | ((unsigned)__bfloat16_as_ushort(ry) << 16);
}

__device__ __forceinline__ void mma16816(float* c, unsigned a0, unsigned a1,
                                         unsigned a2, unsigned a3,
                                         unsigned b0, unsigned b1) {
    asm volatile(
        "mma.sync.aligned.m16n8k16.row.col.f32.bf16.bf16.f32 "
        "{%0,%1,%2,%3}, {%4,%5,%6,%7}, {%8,%9}, {%0,%1,%2,%3};"
        : "+f"(c[0]), "+f"(c[1]), "+f"(c[2]), "+f"(c[3])
        : "r"(a0), "r"(a1), "r"(a2), "r"(a3), "r"(b0), "r"(b1));
}

// ---------------------------------------------------------------------------
// CSR build: histogram -> parallel scan -> scatter
// ---------------------------------------------------------------------------
__global__ void k_zero_cnt() {
    int i = blockIdx.x * blockDim.x + threadIdx.x;
    if (i < N_NODES) g_cnt[i] = 0;
}

__global__ void k_count(const int* __restrict__ ei) {
    int e = blockIdx.x * blockDim.x + threadIdx.x;
    if (e < E_EDGES) atomicAdd(&g_cnt[ei[E_EDGES + e]], 1);
}

__global__ void __launch_bounds__(1024) k_scan_a() {
    __shared__ int sm[1024];
    int t = threadIdx.x;
    int i = blockIdx.x * 1024 + t;
    int v = (i < N_NODES) ? g_cnt[i] : 0;
    sm[t] = v;
    __syncthreads();
#pragma unroll
    for (int off = 1; off < 1024; off <<= 1) {
        int u = (t >= off) ? sm[t - off] : 0;
        __syncthreads();
        sm[t] += u;
        __syncthreads();
    }
    if (i < N_NODES) g_rowptr[i] = sm[t] - v;
    if (t == 1023) g_bsum[blockIdx.x] = sm[1023];
}

__global__ void __launch_bounds__(128) k_scan_b() {
    __shared__ int sm[128];
    int t = threadIdx.x;
    int v = (t < SCAN_BLOCKS) ? g_bsum[t] : 0;
    sm[t] = v;
    __syncthreads();
#pragma unroll
    for (int off = 1; off < 128; off <<= 1) {
        int u = (t >= off) ? sm[t - off] : 0;
        __syncthreads();
        sm[t] += u;
        __syncthreads();
    }
    if (t < SCAN_BLOCKS) g_boff[t] = sm[t] - v;
}

__global__ void __launch_bounds__(1024) k_scan_c() {
    int i = blockIdx.x * 1024 + threadIdx.x;
    if (i < N_NODES) {
        int r = g_rowptr[i] + g_boff[blockIdx.x];
        g_rowptr[i] = r;
        g_cursor[i] = r;
        g_dinv[i] = rsqrtf((float)g_cnt[i] + 1.0f);
    }
    if (i == 0) g_rowptr[N_NODES] = E_EDGES;
}

__global__ void k_scatter(const int* __restrict__ ei) {
    int e = blockIdx.x * blockDim.x + threadIdx.x;
    if (e < E_EDGES) {
        int src = ei[e];
        int dst = ei[E_EDGES + e];
        int pos = atomicAdd(&g_cursor[dst], 1);
        g_csr_src[pos] = src;
    }
}

// ---------------------------------------------------------------------------
// W prep: split W^T into bf16 main + residual, [n][k] layout (col-major B).
// ---------------------------------------------------------------------------
__global__ void k_wprep(const float* __restrict__ W) {
    int t = blockIdx.x * 256 + threadIdx.x;
    if (t >= D * D) return;
    int n = t >> 7, k = t & 127;
    float w = W[k * D + n];
    __nv_bfloat16 m = __float2bfloat16_rn(w);
    __nv_bfloat16 r = __float2bfloat16_rn(w - __bfloat162float(m));
    g_wm[n * D + k] = m;
    g_wr[n * D + k] = r;
}

// ---------------------------------------------------------------------------
// bf16 split-compensated MMA GEMM: g_h = SRC @ W (fp32-equivalent accuracy).
// 256 threads = 8 warps; warp tile 32x32; block tile M=128, N=64.
// Grid x2 over N halves. A fragments straight from global (L2), B from
// pre-split g_wm/g_wr (L1-resident). 3 MMA terms: Am*Bm + Ar*Bm + Am*Br.
// ---------------------------------------------------------------------------
template <bool FROM_TMP>
__global__ void __launch_bounds__(256)
k_gemm_mma(const float* __restrict__ X) {
    const float* src = FROM_TMP ? (const float*)g_tmp : X;
    int tid  = threadIdx.x;
    int warp = tid >> 5, lane = tid & 31;
    int g  = lane >> 2;      // group id (row within fragment)
    int tk = lane & 3;       // thread-in-group
    int mb    = blockIdx.x >> 1;
    int nhalf = blockIdx.x & 1;
    int m0 = mb * 128 + (warp & 3) * 32;          // warp M base
    int n0 = nhalf * 64 + (warp >> 2) * 32;       // warp N base

    float c[2][4][4];
#pragma unroll
    for (int t = 0; t < 2; ++t)
#pragma unroll
        for (int j = 0; j < 4; ++j)
#pragma unroll
            for (int q = 0; q < 4; ++q) c[t][j][q] = 0.0f;

#pragma unroll 1
    for (int kc = 0; kc < 8; ++kc) {
        int kb = kc * 16;

        // A fragments (2 m16 tiles), convert fp32 -> bf16 main+res on the fly
        unsigned am[2][4], ar[2][4];
#pragma unroll
        for (int t = 0; t < 2; ++t) {
            int r0 = m0 + t * 16 + g;
            int r1 = r0 + 8;
            float2 z = make_float2(0.f, 0.f);
            float2 x00 = (r0 < N_NODES) ? *(const float2*)&src[r0 * 128 + kb + tk * 2] : z;
            float2 x10 = (r1 < N_NODES) ? *(const float2*)&src[r1 * 128 + kb + tk * 2] : z;
            float2 x01 = (r0 < N_NODES) ? *(const float2*)&src[r0 * 128 + kb + 8 + tk * 2] : z;
            float2 x11 = (r1 < N_NODES) ? *(const float2*)&src[r1 * 128 + kb + 8 + tk * 2] : z;
            split2(x00, am[t][0], ar[t][0]);
            split2(x10, am[t][1], ar[t][1]);
            split2(x01, am[t][2], ar[t][2]);
            split2(x11, am[t][3], ar[t][3]);
        }

        // B fragments (4 n8 tiles) from pre-split bf16 W^T [n][k]
        unsigned bm[4][2], br[4][2];
#pragma unroll
        for (int j = 0; j < 4; ++j) {
            int n = n0 + j * 8 + g;
            int off = n * 128 + kb + tk * 2;
            bm[j][0] = *(const unsigned*)&g_wm[off];
            bm[j][1] = *(const unsigned*)&g_wm[off + 8];
            br[j][0] = *(const unsigned*)&g_wr[off];
            br[j][1] = *(const unsigned*)&g_wr[off + 8];
        }

#pragma unroll
        for (int t = 0; t < 2; ++t)
#pragma unroll
            for (int j = 0; j < 4; ++j) {
                mma16816(c[t][j], am[t][0], am[t][1], am[t][2], am[t][3],
                         bm[j][0], bm[j][1]);
                mma16816(c[t][j], ar[t][0], ar[t][1], ar[t][2], ar[t][3],
                         bm[j][0], bm[j][1]);
                mma16816(c[t][j], am[t][0], am[t][1], am[t][2], am[t][3],
                         br[j][0], br[j][1]);
            }
    }

    // Store D
#pragma unroll
    for (int t = 0; t < 2; ++t) {
        int r0 = m0 + t * 16 + g;
        int r1 = r0 + 8;
#pragma unroll
        for (int j = 0; j < 4; ++j) {
            int col = n0 + j * 8 + tk * 2;
            if (r0 < N_NODES)
                *(float2*)&g_h[r0 * 128 + col] = make_float2(c[t][j][0], c[t][j][1]);
            if (r1 < N_NODES)
                *(float2*)&g_h[r1 * 128 + col] = make_float2(c[t][j][2], c[t][j][3]);
        }
    }
}

// ---------------------------------------------------------------------------
// Aggregation: one warp per dst node (unchanged from R5)
// ---------------------------------------------------------------------------
template <bool TO_OUT>
__global__ void __launch_bounds__(256)
k_agg(const float* __restrict__ b, float* __restrict__ OUT) {
    int node = blockIdx.x * 8 + (threadIdx.x >> 5);
    int lane = threadIdx.x & 31;
    if (node >= N_NODES) return;

    float* dst_buf = TO_OUT ? OUT : (float*)g_tmp;
    const float4* Hv = (const float4*)g_h;

    float dv = g_dinv[node];
    float4 acc = Hv[node * 32 + lane];
    acc.x *= dv; acc.y *= dv; acc.z *= dv; acc.w *= dv;

    int j = g_rowptr[node];
    int end = g_rowptr[node + 1];

    while (j < end) {
        int take = end - j;
        if (take > 32) take = 32;
        int   sidx = 0;
        float snrm = 0.0f;
        if (lane < take) {
            sidx = g_csr_src[j + lane];
            snrm = g_dinv[sidx];
        }
#pragma unroll 4
        for (int t = 0; t < take; ++t) {
            int   s = __shfl_sync(0xffffffffu, sidx, t);
            float n = __shfl_sync(0xffffffffu, snrm, t);
            float4 h = Hv[s * 32 + lane];
            acc.x = fmaf(n, h.x, acc.x);
            acc.y = fmaf(n, h.y, acc.y);
            acc.z = fmaf(n, h.z, acc.z);
            acc.w = fmaf(n, h.w, acc.w);
        }
        j += take;
    }

    float4 bb = *(const float4*)&b[lane * 4];
    acc.x = fmaxf(fmaf(dv, acc.x, bb.x), 0.f);
    acc.y = fmaxf(fmaf(dv, acc.y, bb.y), 0.f);
    acc.z = fmaxf(fmaf(dv, acc.z, bb.z), 0.f);
    acc.w = fmaxf(fmaf(dv, acc.w, bb.w), 0.f);
    ((float4*)dst_buf)[node * 32 + lane] = acc;
}

// ---------------------------------------------------------------------------
extern "C" void kernel_launch(void* const* d_in, const int* in_sizes, int n_in,
                              void* d_out, int out_size) {
    const float* x  = (const float*)d_in[0];
    const int*   ei = (const int*)d_in[1];
    const float* W1 = (const float*)d_in[2];
    const float* b1 = (const float*)d_in[3];
    const float* W2 = (const float*)d_in[4];
    const float* b2 = (const float*)d_in[5];
    const float* W3 = (const float*)d_in[6];
    const float* b3 = (const float*)d_in[7];
    float* out = (float*)d_out;

    // CSR build
    k_zero_cnt<<<(N_NODES + 255) / 256, 256>>>();
    k_count<<<(E_EDGES + 255) / 256, 256>>>(ei);
    k_scan_a<<<SCAN_BLOCKS, 1024>>>();
    k_scan_b<<<1, 128>>>();
    k_scan_c<<<SCAN_BLOCKS, 1024>>>();
    k_scatter<<<(E_EDGES + 255) / 256, 256>>>(ei);

    const int gemm_blocks = ((N_NODES + 127) / 128) * 2;   // 1564
    const int agg_blocks  = (N_NODES + 7) / 8;
    const int wprep_blocks = (D * D + 255) / 256;

    // Layer 1: x -> g_h -> g_tmp
    k_wprep<<<wprep_blocks, 256>>>(W1);
    k_gemm_mma<false><<<gemm_blocks, 256>>>(x);
    k_agg<false><<<agg_blocks, 256>>>(b1, nullptr);
    // Layer 2: g_tmp -> g_h -> g_tmp
    k_wprep<<<wprep_blocks, 256>>>(W2);
    k_gemm_mma<true><<<gemm_blocks, 256>>>(nullptr);
    k_agg<false><<<agg_blocks, 256>>>(b2, nullptr);
    // Layer 3: g_tmp -> g_h -> out
    k_wprep<<<wprep_blocks, 256>>>(W3);
    k_gemm_mma<true><<<gemm_blocks, 256>>>(nullptr);
    k_agg<true><<<agg_blocks, 256>>>(b3, out);
}

// round 8
// speedup vs baseline: 1.7378x; 1.1534x over previous
#include <cuda_runtime.h>
#include <cuda_bf16.h>
#include <cuda_fp16.h>

#define N_NODES 100000
#define D 128
#define E_EDGES 1600000
#define SCAN_BLOCKS ((N_NODES + 1023) / 1024)   // 98

// Scratch (device globals; no runtime allocation allowed)
__device__ __half g_hh[N_NODES * D];   // pre-normalized messages dinv[m]*H[m], fp16
__device__ float g_tmp[N_NODES * D];   // layer output / next layer input
__device__ float g_dinv[N_NODES];
__device__ int   g_cnt[N_NODES];
__device__ int   g_rowptr[N_NODES + 1];
__device__ int   g_cursor[N_NODES];
__device__ int   g_csr_src[E_EDGES];
__device__ int   g_bsum[SCAN_BLOCKS];
__device__ int   g_boff[SCAN_BLOCKS];
__device__ __nv_bfloat16 g_wm[D * D];  // W^T main bf16, [n][k] (k contiguous)
__device__ __nv_bfloat16 g_wr[D * D];  // W^T residual bf16

// ---------------------------------------------------------------------------
// Helpers
// ---------------------------------------------------------------------------
__device__ __forceinline__ void split2(float2 v, unsigned& m, unsigned& r) {
    __nv_bfloat16 mx = __float2bfloat16_rn(v.x);
    __nv_bfloat16 my = __float2bfloat16_rn(v.y);
    __nv_bfloat16 rx = __float2bfloat16_rn(v.x - __bfloat162float(mx));
    __nv_bfloat16 ry = __float2bfloat16_rn(v.y - __bfloat162float(my));
    m = (unsigned)__bfloat16_as_ushort(mx) | ((unsigned)__bfloat16_as_ushort(my) << 16);
    r = (unsigned)__bfloat16_as_ushort(rx) | ((unsigned)__bfloat16_as_ushort(ry) << 16);
}

__device__ __forceinline__ void mma16816(float* c, unsigned a0, unsigned a1,
                                         unsigned a2, unsigned a3,
                                         unsigned b0, unsigned b1) {
    asm volatile(
        "mma.sync.aligned.m16n8k16.row.col.f32.bf16.bf16.f32 "
        "{%0,%1,%2,%3}, {%4,%5,%6,%7}, {%8,%9}, {%0,%1,%2,%3};"
        : "+f"(c[0]), "+f"(c[1]), "+f"(c[2]), "+f"(c[3])
        : "r"(a0), "r"(a1), "r"(a2), "r"(a3), "r"(b0), "r"(b1));
}

// ---------------------------------------------------------------------------
// CSR build: histogram -> parallel scan -> scatter
// ---------------------------------------------------------------------------
__global__ void k_zero_cnt() {
    int i = blockIdx.x * blockDim.x + threadIdx.x;
    if (i < N_NODES) g_cnt[i] = 0;
}

__global__ void k_count(const int* __restrict__ ei) {
    int e = blockIdx.x * blockDim.x + threadIdx.x;
    if (e < E_EDGES) atomicAdd(&g_cnt[ei[E_EDGES + e]], 1);
}

__global__ void __launch_bounds__(1024) k_scan_a() {
    __shared__ int sm[1024];
    int t = threadIdx.x;
    int i = blockIdx.x * 1024 + t;
    int v = (i < N_NODES) ? g_cnt[i] : 0;
    sm[t] = v;
    __syncthreads();
#pragma unroll
    for (int off = 1; off < 1024; off <<= 1) {
        int u = (t >= off) ? sm[t - off] : 0;
        __syncthreads();
        sm[t] += u;
        __syncthreads();
    }
    if (i < N_NODES) g_rowptr[i] = sm[t] - v;
    if (t == 1023) g_bsum[blockIdx.x] = sm[1023];
}

__global__ void __launch_bounds__(128) k_scan_b() {
    __shared__ int sm[128];
    int t = threadIdx.x;
    int v = (t < SCAN_BLOCKS) ? g_bsum[t] : 0;
    sm[t] = v;
    __syncthreads();
#pragma unroll
    for (int off = 1; off < 128; off <<= 1) {
        int u = (t >= off) ? sm[t - off] : 0;
        __syncthreads();
        sm[t] += u;
        __syncthreads();
    }
    if (t < SCAN_BLOCKS) g_boff[t] = sm[t] - v;
}

__global__ void __launch_bounds__(1024) k_scan_c() {
    int i = blockIdx.x * 1024 + threadIdx.x;
    if (i < N_NODES) {
        int r = g_rowptr[i] + g_boff[blockIdx.x];
        g_rowptr[i] = r;
        g_cursor[i] = r;
        g_dinv[i] = rsqrtf((float)g_cnt[i] + 1.0f);
    }
    if (i == 0) g_rowptr[N_NODES] = E_EDGES;
}

__global__ void k_scatter(const int* __restrict__ ei) {
    int e = blockIdx.x * blockDim.x + threadIdx.x;
    if (e < E_EDGES) {
        int src = ei[e];
        int dst = ei[E_EDGES + e];
        int pos = atomicAdd(&g_cursor[dst], 1);
        g_csr_src[pos] = src;
    }
}

// ---------------------------------------------------------------------------
// W prep: split W^T into bf16 main + residual, [n][k] layout (col-major B).
// ---------------------------------------------------------------------------
__global__ void k_wprep(const float* __restrict__ W) {
    int t = blockIdx.x * 256 + threadIdx.x;
    if (t >= D * D) return;
    int n = t >> 7, k = t & 127;
    float w = W[k * D + n];
    __nv_bfloat16 m = __float2bfloat16_rn(w);
    __nv_bfloat16 r = __float2bfloat16_rn(w - __bfloat162float(m));
    g_wm[n * D + k] = m;
    g_wr[n * D + k] = r;
}

// ---------------------------------------------------------------------------
// bf16 split-compensated MMA GEMM, epilogue stores dinv[m]*(SRC@W) as fp16.
// 256 threads = 8 warps; warp tile 32x32; block tile M=128, N=64; grid x2 N.
// ---------------------------------------------------------------------------
template <bool FROM_TMP>
__global__ void __launch_bounds__(256)
k_gemm_mma(const float* __restrict__ X) {
    const float* src = FROM_TMP ? (const float*)g_tmp : X;
    int tid  = threadIdx.x;
    int warp = tid >> 5, lane = tid & 31;
    int g  = lane >> 2;      // group id (row within fragment)
    int tk = lane & 3;       // thread-in-group
    int mb    = blockIdx.x >> 1;
    int nhalf = blockIdx.x & 1;
    int m0 = mb * 128 + (warp & 3) * 32;          // warp M base
    int n0 = nhalf * 64 + (warp >> 2) * 32;       // warp N base

    float c[2][4][4];
#pragma unroll
    for (int t = 0; t < 2; ++t)
#pragma unroll
        for (int j = 0; j < 4; ++j)
#pragma unroll
            for (int q = 0; q < 4; ++q) c[t][j][q] = 0.0f;

#pragma unroll 1
    for (int kc = 0; kc < 8; ++kc) {
        int kb = kc * 16;

        unsigned am[2][4], ar[2][4];
#pragma unroll
        for (int t = 0; t < 2; ++t) {
            int r0 = m0 + t * 16 + g;
            int r1 = r0 + 8;
            float2 z = make_float2(0.f, 0.f);
            float2 x00 = (r0 < N_NODES) ? *(const float2*)&src[r0 * 128 + kb + tk * 2] : z;
            float2 x10 = (r1 < N_NODES) ? *(const float2*)&src[r1 * 128 + kb + tk * 2] : z;
            float2 x01 = (r0 < N_NODES) ? *(const float2*)&src[r0 * 128 + kb + 8 + tk * 2] : z;
            float2 x11 = (r1 < N_NODES) ? *(const float2*)&src[r1 * 128 + kb + 8 + tk * 2] : z;
            split2(x00, am[t][0], ar[t][0]);
            split2(x10, am[t][1], ar[t][1]);
            split2(x01, am[t][2], ar[t][2]);
            split2(x11, am[t][3], ar[t][3]);
        }

        unsigned bm[4][2], br[4][2];
#pragma unroll
        for (int j = 0; j < 4; ++j) {
            int n = n0 + j * 8 + g;
            int off = n * 128 + kb + tk * 2;
            bm[j][0] = *(const unsigned*)&g_wm[off];
            bm[j][1] = *(const unsigned*)&g_wm[off + 8];
            br[j][0] = *(const unsigned*)&g_wr[off];
            br[j][1] = *(const unsigned*)&g_wr[off + 8];
        }

#pragma unroll
        for (int t = 0; t < 2; ++t)
#pragma unroll
            for (int j = 0; j < 4; ++j) {
                mma16816(c[t][j], am[t][0], am[t][1], am[t][2], am[t][3],
                         bm[j][0], bm[j][1]);
                mma16816(c[t][j], ar[t][0], ar[t][1], ar[t][2], ar[t][3],
                         bm[j][0], bm[j][1]);
                mma16816(c[t][j], am[t][0], am[t][1], am[t][2], am[t][3],
                         br[j][0], br[j][1]);
            }
    }

    // Epilogue: scale by dinv[row], store fp16
#pragma unroll
    for (int t = 0; t < 2; ++t) {
        int r0 = m0 + t * 16 + g;
        int r1 = r0 + 8;
        float dv0 = (r0 < N_NODES) ? g_dinv[r0] : 0.f;
        float dv1 = (r1 < N_NODES) ? g_dinv[r1] : 0.f;
#pragma unroll
        for (int j = 0; j < 4; ++j) {
            int col = n0 + j * 8 + tk * 2;
            if (r0 < N_NODES)
                *(__half2*)&g_hh[r0 * 128 + col] =
                    __floats2half2_rn(dv0 * c[t][j][0], dv0 * c[t][j][1]);
            if (r1 < N_NODES)
                *(__half2*)&g_hh[r1 * 128 + col] =
                    __floats2half2_rn(dv1 * c[t][j][2], dv1 * c[t][j][3]);
        }
    }
}

// ---------------------------------------------------------------------------
// Aggregation: one warp per dst node; lane owns 4 halves (8B) of the row.
// out[dst] = relu( dinv[dst] * ( sum_src H'[src] + H'[dst] ) + b ),
// where H' = dinv*H is pre-scaled fp16 -> plain adds, no per-edge dinv.
// ---------------------------------------------------------------------------
template <bool TO_OUT>
__global__ void __launch_bounds__(256)
k_agg(const float* __restrict__ b, float* __restrict__ OUT) {
    int node = blockIdx.x * 8 + (threadIdx.x >> 5);
    int lane = threadIdx.x & 31;
    if (node >= N_NODES) return;

    float* dst_buf = TO_OUT ? OUT : (float*)g_tmp;
    const uint2* Hv = (const uint2*)g_hh;   // 32 x 8B per 128-half row

    float dv = g_dinv[node];
    uint2 sraw = Hv[node * 32 + lane];
    float2 p0 = __half22float2(*(__half2*)&sraw.x);
    float2 p1 = __half22float2(*(__half2*)&sraw.y);
    float a0 = p0.x, a1 = p0.y, a2 = p1.x, a3 = p1.y;  // self term H'[dst]

    int j = g_rowptr[node];
    int end = g_rowptr[node + 1];

    while (j < end) {
        int take = end - j;
        if (take > 32) take = 32;
        int sidx = (lane < take) ? g_csr_src[j + lane] : 0;
#pragma unroll 4
        for (int t = 0; t < take; ++t) {
            int s = __shfl_sync(0xffffffffu, sidx, t);
            uint2 raw = Hv[s * 32 + lane];
            float2 q0 = __half22float2(*(__half2*)&raw.x);
            float2 q1 = __half22float2(*(__half2*)&raw.y);
            a0 += q0.x; a1 += q0.y; a2 += q1.x; a3 += q1.y;
        }
        j += take;
    }

    float4 bb = *(const float4*)&b[lane * 4];
    float4 o;
    o.x = fmaxf(fmaf(dv, a0, bb.x), 0.f);
    o.y = fmaxf(fmaf(dv, a1, bb.y), 0.f);
    o.z = fmaxf(fmaf(dv, a2, bb.z), 0.f);
    o.w = fmaxf(fmaf(dv, a3, bb.w), 0.f);
    ((float4*)dst_buf)[node * 32 + lane] = o;
}

// ---------------------------------------------------------------------------
extern "C" void kernel_launch(void* const* d_in, const int* in_sizes, int n_in,
                              void* d_out, int out_size) {
    const float* x  = (const float*)d_in[0];
    const int*   ei = (const int*)d_in[1];
    const float* W1 = (const float*)d_in[2];
    const float* b1 = (const float*)d_in[3];
    const float* W2 = (const float*)d_in[4];
    const float* b2 = (const float*)d_in[5];
    const float* W3 = (const float*)d_in[6];
    const float* b3 = (const float*)d_in[7];
    float* out = (float*)d_out;

    // CSR build (dinv needed by GEMM epilogue -> keep before layer 1)
    k_zero_cnt<<<(N_NODES + 255) / 256, 256>>>();
    k_count<<<(E_EDGES + 255) / 256, 256>>>(ei);
    k_scan_a<<<SCAN_BLOCKS, 1024>>>();
    k_scan_b<<<1, 128>>>();
    k_scan_c<<<SCAN_BLOCKS, 1024>>>();
    k_scatter<<<(E_EDGES + 255) / 256, 256>>>(ei);

    const int gemm_blocks = ((N_NODES + 127) / 128) * 2;   // 1564
    const int agg_blocks  = (N_NODES + 7) / 8;
    const int wprep_blocks = (D * D + 255) / 256;

    // Layer 1: x -> g_hh -> g_tmp
    k_wprep<<<wprep_blocks, 256>>>(W1);
    k_gemm_mma<false><<<gemm_blocks, 256>>>(x);
    k_agg<false><<<agg_blocks, 256>>>(b1, nullptr);
    // Layer 2: g_tmp -> g_hh -> g_tmp
    k_wprep<<<wprep_blocks, 256>>>(W2);
    k_gemm_mma<true><<<gemm_blocks, 256>>>(nullptr);
    k_agg<false><<<agg_blocks, 256>>>(b2, nullptr);
    // Layer 3: g_tmp -> g_hh -> out
    k_wprep<<<wprep_blocks, 256>>>(W3);
    k_gemm_mma<true><<<gemm_blocks, 256>>>(nullptr);
    k_agg<true><<<agg_blocks, 256>>>(b3, out);
}

// round 9
// speedup vs baseline: 1.8008x; 1.0363x over previous
#include <cuda_runtime.h>
#include <cuda_bf16.h>
#include <cuda_fp16.h>

#define N_NODES 100000
#define D 128
#define E_EDGES 1600000
#define SCAN_BLOCKS ((N_NODES + 1023) / 1024)   // 98

// Scratch (device globals; no runtime allocation allowed)
__device__ __half g_hh[N_NODES * D];   // pre-normalized messages dinv*H, fp16
__device__ __half g_act[N_NODES * D];  // layer activations (fp16), input to GEMM 2/3
__device__ float g_dinv[N_NODES];
__device__ int   g_cnt[N_NODES];
__device__ int   g_rowptr[N_NODES + 1];
__device__ int   g_cursor[N_NODES];
__device__ int   g_csr_src[E_EDGES];
__device__ int   g_bsum[SCAN_BLOCKS];
__device__ int   g_boff[SCAN_BLOCKS];
__device__ __nv_bfloat16 g_wm[D * D];  // W^T main bf16 [n][k] (layer 1)
__device__ __nv_bfloat16 g_wr[D * D];  // W^T residual bf16 (layer 1)
__device__ __half g_wmh[D * D];        // W^T main fp16 [n][k] (layers 2,3)
__device__ __half g_wrh[D * D];        // W^T residual fp16 (layers 2,3)

// ---------------------------------------------------------------------------
// Helpers
// ---------------------------------------------------------------------------
__device__ __forceinline__ void split2(float2 v, unsigned& m, unsigned& r) {
    __nv_bfloat16 mx = __float2bfloat16_rn(v.x);
    __nv_bfloat16 my = __float2bfloat16_rn(v.y);
    __nv_bfloat16 rx = __float2bfloat16_rn(v.x - __bfloat162float(mx));
    __nv_bfloat16 ry = __float2bfloat16_rn(v.y - __bfloat162float(my));
    m = (unsigned)__bfloat16_as_ushort(mx) | ((unsigned)__bfloat16_as_ushort(my) << 16);
    r = (unsigned)__bfloat16_as_ushort(rx) | ((unsigned)__bfloat16_as_ushort(ry) << 16);
}

__device__ __forceinline__ void mma_bf16(float* c, unsigned a0, unsigned a1,
                                         unsigned a2, unsigned a3,
                                         unsigned b0, unsigned b1) {
    asm volatile(
        "mma.sync.aligned.m16n8k16.row.col.f32.bf16.bf16.f32 "
        "{%0,%1,%2,%3}, {%4,%5,%6,%7}, {%8,%9}, {%0,%1,%2,%3};"
        : "+f"(c[0]), "+f"(c[1]), "+f"(c[2]), "+f"(c[3])
        : "r"(a0), "r"(a1), "r"(a2), "r"(a3), "r"(b0), "r"(b1));
}

__device__ __forceinline__ void mma_f16(float* c, unsigned a0, unsigned a1,
                                        unsigned a2, unsigned a3,
                                        unsigned b0, unsigned b1) {
    asm volatile(
        "mma.sync.aligned.m16n8k16.row.col.f32.f16.f16.f32 "
        "{%0,%1,%2,%3}, {%4,%5,%6,%7}, {%8,%9}, {%0,%1,%2,%3};"
        : "+f"(c[0]), "+f"(c[1]), "+f"(c[2]), "+f"(c[3])
        : "r"(a0), "r"(a1), "r"(a2), "r"(a3), "r"(b0), "r"(b1));
}

// ---------------------------------------------------------------------------
// CSR build: histogram -> parallel scan -> scatter
// ---------------------------------------------------------------------------
__global__ void k_zero_cnt() {
    int i = blockIdx.x * blockDim.x + threadIdx.x;
    if (i < N_NODES) g_cnt[i] = 0;
}

__global__ void k_count(const int* __restrict__ ei) {
    int e = blockIdx.x * blockDim.x + threadIdx.x;
    if (e < E_EDGES) atomicAdd(&g_cnt[ei[E_EDGES + e]], 1);
}

__global__ void __launch_bounds__(1024) k_scan_a() {
    __shared__ int sm[1024];
    int t = threadIdx.x;
    int i = blockIdx.x * 1024 + t;
    int v = (i < N_NODES) ? g_cnt[i] : 0;
    sm[t] = v;
    __syncthreads();
#pragma unroll
    for (int off = 1; off < 1024; off <<= 1) {
        int u = (t >= off) ? sm[t - off] : 0;
        __syncthreads();
        sm[t] += u;
        __syncthreads();
    }
    if (i < N_NODES) g_rowptr[i] = sm[t] - v;
    if (t == 1023) g_bsum[blockIdx.x] = sm[1023];
}

__global__ void __launch_bounds__(128) k_scan_b() {
    __shared__ int sm[128];
    int t = threadIdx.x;
    int v = (t < SCAN_BLOCKS) ? g_bsum[t] : 0;
    sm[t] = v;
    __syncthreads();
#pragma unroll
    for (int off = 1; off < 128; off <<= 1) {
        int u = (t >= off) ? sm[t - off] : 0;
        __syncthreads();
        sm[t] += u;
        __syncthreads();
    }
    if (t < SCAN_BLOCKS) g_boff[t] = sm[t] - v;
}

__global__ void __launch_bounds__(1024) k_scan_c() {
    int i = blockIdx.x * 1024 + threadIdx.x;
    if (i < N_NODES) {
        int r = g_rowptr[i] + g_boff[blockIdx.x];
        g_rowptr[i] = r;
        g_cursor[i] = r;
        g_dinv[i] = rsqrtf((float)g_cnt[i] + 1.0f);
    }
    if (i == 0) g_rowptr[N_NODES] = E_EDGES;
}

__global__ void k_scatter(const int* __restrict__ ei) {
    int e = blockIdx.x * blockDim.x + threadIdx.x;
    if (e < E_EDGES) {
        int src = ei[e];
        int dst = ei[E_EDGES + e];
        int pos = atomicAdd(&g_cursor[dst], 1);
        g_csr_src[pos] = src;
    }
}

// ---------------------------------------------------------------------------
// W prep: split W^T into main + residual, [n][k] layout (col-major B).
// ---------------------------------------------------------------------------
__global__ void k_wprep_bf16(const float* __restrict__ W) {
    int t = blockIdx.x * 256 + threadIdx.x;
    if (t >= D * D) return;
    int n = t >> 7, k = t & 127;
    float w = W[k * D + n];
    __nv_bfloat16 m = __float2bfloat16_rn(w);
    __nv_bfloat16 r = __float2bfloat16_rn(w - __bfloat162float(m));
    g_wm[n * D + k] = m;
    g_wr[n * D + k] = r;
}

__global__ void k_wprep_f16(const float* __restrict__ W) {
    int t = blockIdx.x * 256 + threadIdx.x;
    if (t >= D * D) return;
    int n = t >> 7, k = t & 127;
    float w = W[k * D + n];
    __half m = __float2half_rn(w);
    __half r = __float2half_rn(w - __half2float(m));
    g_wmh[n * D + k] = m;
    g_wrh[n * D + k] = r;
}

// ---------------------------------------------------------------------------
// Layer-1 GEMM: bf16 split-compensated (A from fp32 x), 3 MMA terms.
// 8 warps; warp tile 32x32; block M=128, N=64; grid x2 over N halves.
// Epilogue stores dinv[m]*(x@W) as fp16 into g_hh.
// ---------------------------------------------------------------------------
__global__ void __launch_bounds__(256)
k_gemm_l1(const float* __restrict__ X) {
    int tid  = threadIdx.x;
    int warp = tid >> 5, lane = tid & 31;
    int g  = lane >> 2;
    int tk = lane & 3;
    int mb    = blockIdx.x >> 1;
    int nhalf = blockIdx.x & 1;
    int m0 = mb * 128 + (warp & 3) * 32;
    int n0 = nhalf * 64 + (warp >> 2) * 32;

    float c[2][4][4];
#pragma unroll
    for (int t = 0; t < 2; ++t)
#pragma unroll
        for (int j = 0; j < 4; ++j)
#pragma unroll
            for (int q = 0; q < 4; ++q) c[t][j][q] = 0.0f;

#pragma unroll 1
    for (int kc = 0; kc < 8; ++kc) {
        int kb = kc * 16;

        unsigned am[2][4], ar[2][4];
#pragma unroll
        for (int t = 0; t < 2; ++t) {
            int r0 = m0 + t * 16 + g;
            int r1 = r0 + 8;
            float2 z = make_float2(0.f, 0.f);
            float2 x00 = (r0 < N_NODES) ? *(const float2*)&X[r0 * 128 + kb + tk * 2] : z;
            float2 x10 = (r1 < N_NODES) ? *(const float2*)&X[r1 * 128 + kb + tk * 2] : z;
            float2 x01 = (r0 < N_NODES) ? *(const float2*)&X[r0 * 128 + kb + 8 + tk * 2] : z;
            float2 x11 = (r1 < N_NODES) ? *(const float2*)&X[r1 * 128 + kb + 8 + tk * 2] : z;
            split2(x00, am[t][0], ar[t][0]);
            split2(x10, am[t][1], ar[t][1]);
            split2(x01, am[t][2], ar[t][2]);
            split2(x11, am[t][3], ar[t][3]);
        }

        unsigned bm[4][2], br[4][2];
#pragma unroll
        for (int j = 0; j < 4; ++j) {
            int n = n0 + j * 8 + g;
            int off = n * 128 + kb + tk * 2;
            bm[j][0] = *(const unsigned*)&g_wm[off];
            bm[j][1] = *(const unsigned*)&g_wm[off + 8];
            br[j][0] = *(const unsigned*)&g_wr[off];
            br[j][1] = *(const unsigned*)&g_wr[off + 8];
        }

#pragma unroll
        for (int t = 0; t < 2; ++t)
#pragma unroll
            for (int j = 0; j < 4; ++j) {
                mma_bf16(c[t][j], am[t][0], am[t][1], am[t][2], am[t][3],
                         bm[j][0], bm[j][1]);
                mma_bf16(c[t][j], ar[t][0], ar[t][1], ar[t][2], ar[t][3],
                         bm[j][0], bm[j][1]);
                mma_bf16(c[t][j], am[t][0], am[t][1], am[t][2], am[t][3],
                         br[j][0], br[j][1]);
            }
    }

#pragma unroll
    for (int t = 0; t < 2; ++t) {
        int r0 = m0 + t * 16 + g;
        int r1 = r0 + 8;
        float dv0 = (r0 < N_NODES) ? g_dinv[r0] : 0.f;
        float dv1 = (r1 < N_NODES) ? g_dinv[r1] : 0.f;
#pragma unroll
        for (int j = 0; j < 4; ++j) {
            int col = n0 + j * 8 + tk * 2;
            if (r0 < N_NODES)
                *(__half2*)&g_hh[r0 * 128 + col] =
                    __floats2half2_rn(dv0 * c[t][j][0], dv0 * c[t][j][1]);
            if (r1 < N_NODES)
                *(__half2*)&g_hh[r1 * 128 + col] =
                    __floats2half2_rn(dv1 * c[t][j][2], dv1 * c[t][j][3]);
        }
    }
}

// ---------------------------------------------------------------------------
// Layers 2/3 GEMM: A fp16-exact from g_act, W fp16 main+res, 2 MMA terms.
// 8 warps; warp tile 32x64; block M=128, full N=128 (A read once).
// Epilogue stores dinv[m]*(A@W) as fp16 into g_hh.
// ---------------------------------------------------------------------------
__global__ void __launch_bounds__(256)
k_gemm_h() {
    int tid  = threadIdx.x;
    int warp = tid >> 5, lane = tid & 31;
    int g  = lane >> 2;
    int tk = lane & 3;
    int m0 = blockIdx.x * 128 + (warp & 3) * 32;
    int n0 = (warp >> 2) * 64;

    float c[2][8][4];
#pragma unroll
    for (int t = 0; t < 2; ++t)
#pragma unroll
        for (int j = 0; j < 8; ++j)
#pragma unroll
            for (int q = 0; q < 4; ++q) c[t][j][q] = 0.0f;

#pragma unroll 1
    for (int kc = 0; kc < 8; ++kc) {
        int kb = kc * 16;

        unsigned a[2][4];
#pragma unroll
        for (int t = 0; t < 2; ++t) {
            int r0 = m0 + t * 16 + g;
            int r1 = r0 + 8;
            a[t][0] = (r0 < N_NODES) ? *(const unsigned*)&g_act[r0 * 128 + kb + tk * 2] : 0u;
            a[t][1] = (r1 < N_NODES) ? *(const unsigned*)&g_act[r1 * 128 + kb + tk * 2] : 0u;
            a[t][2] = (r0 < N_NODES) ? *(const unsigned*)&g_act[r0 * 128 + kb + 8 + tk * 2] : 0u;
            a[t][3] = (r1 < N_NODES) ? *(const unsigned*)&g_act[r1 * 128 + kb + 8 + tk * 2] : 0u;
        }

        unsigned bm[8][2], br[8][2];
#pragma unroll
        for (int j = 0; j < 8; ++j) {
            int n = n0 + j * 8 + g;
            int off = n * 128 + kb + tk * 2;
            bm[j][0] = *(const unsigned*)&g_wmh[off];
            bm[j][1] = *(const unsigned*)&g_wmh[off + 8];
            br[j][0] = *(const unsigned*)&g_wrh[off];
            br[j][1] = *(const unsigned*)&g_wrh[off + 8];
        }

#pragma unroll
        for (int t = 0; t < 2; ++t)
#pragma unroll
            for (int j = 0; j < 8; ++j) {
                mma_f16(c[t][j], a[t][0], a[t][1], a[t][2], a[t][3],
                        bm[j][0], bm[j][1]);
                mma_f16(c[t][j], a[t][0], a[t][1], a[t][2], a[t][3],
                        br[j][0], br[j][1]);
            }
    }

#pragma unroll
    for (int t = 0; t < 2; ++t) {
        int r0 = m0 + t * 16 + g;
        int r1 = r0 + 8;
        float dv0 = (r0 < N_NODES) ? g_dinv[r0] : 0.f;
        float dv1 = (r1 < N_NODES) ? g_dinv[r1] : 0.f;
#pragma unroll
        for (int j = 0; j < 8; ++j) {
            int col = n0 + j * 8 + tk * 2;
            if (r0 < N_NODES)
                *(__half2*)&g_hh[r0 * 128 + col] =
                    __floats2half2_rn(dv0 * c[t][j][0], dv0 * c[t][j][1]);
            if (r1 < N_NODES)
                *(__half2*)&g_hh[r1 * 128 + col] =
                    __floats2half2_rn(dv1 * c[t][j][2], dv1 * c[t][j][3]);
        }
    }
}

// ---------------------------------------------------------------------------
// Aggregation: one warp per dst node; lane owns 4 halves (8B) of the row.
// out[dst] = relu( dinv[dst] * ( sum_src H'[src] + H'[dst] ) + b ).
// TO_OUT=false -> fp16 activations g_act; TO_OUT=true -> fp32 OUT.
// ---------------------------------------------------------------------------
template <bool TO_OUT>
__global__ void __launch_bounds__(256)
k_agg(const float* __restrict__ b, float* __restrict__ OUT) {
    int node = blockIdx.x * 8 + (threadIdx.x >> 5);
    int lane = threadIdx.x & 31;
    if (node >= N_NODES) return;

    const uint2* Hv = (const uint2*)g_hh;

    float dv = g_dinv[node];
    uint2 sraw = Hv[node * 32 + lane];
    float2 p0 = __half22float2(*(__half2*)&sraw.x);
    float2 p1 = __half22float2(*(__half2*)&sraw.y);
    float a0 = p0.x, a1 = p0.y, a2 = p1.x, a3 = p1.y;

    int j = g_rowptr[node];
    int end = g_rowptr[node + 1];

    while (j < end) {
        int take = end - j;
        if (take > 32) take = 32;
        int sidx = (lane < take) ? g_csr_src[j + lane] : 0;
#pragma unroll 4
        for (int t = 0; t < take; ++t) {
            int s = __shfl_sync(0xffffffffu, sidx, t);
            uint2 raw = Hv[s * 32 + lane];
            float2 q0 = __half22float2(*(__half2*)&raw.x);
            float2 q1 = __half22float2(*(__half2*)&raw.y);
            a0 += q0.x; a1 += q0.y; a2 += q1.x; a3 += q1.y;
        }
        j += take;
    }

    float4 bb = *(const float4*)&b[lane * 4];
    float o0 = fmaxf(fmaf(dv, a0, bb.x), 0.f);
    float o1 = fmaxf(fmaf(dv, a1, bb.y), 0.f);
    float o2 = fmaxf(fmaf(dv, a2, bb.z), 0.f);
    float o3 = fmaxf(fmaf(dv, a3, bb.w), 0.f);

    if (TO_OUT) {
        ((float4*)OUT)[node * 32 + lane] = make_float4(o0, o1, o2, o3);
    } else {
        uint2 w;
        *(__half2*)&w.x = __floats2half2_rn(o0, o1);
        *(__half2*)&w.y = __floats2half2_rn(o2, o3);
        ((uint2*)g_act)[node * 32 + lane] = w;
    }
}

// ---------------------------------------------------------------------------
extern "C" void kernel_launch(void* const* d_in, const int* in_sizes, int n_in,
                              void* d_out, int out_size) {
    const float* x  = (const float*)d_in[0];
    const int*   ei = (const int*)d_in[1];
    const float* W1 = (const float*)d_in[2];
    const float* b1 = (const float*)d_in[3];
    const float* W2 = (const float*)d_in[4];
    const float* b2 = (const float*)d_in[5];
    const float* W3 = (const float*)d_in[6];
    const float* b3 = (const float*)d_in[7];
    float* out = (float*)d_out;

    // CSR build (dinv needed by GEMM epilogue)
    k_zero_cnt<<<(N_NODES + 255) / 256, 256>>>();
    k_count<<<(E_EDGES + 255) / 256, 256>>>(ei);
    k_scan_a<<<SCAN_BLOCKS, 1024>>>();
    k_scan_b<<<1, 128>>>();
    k_scan_c<<<SCAN_BLOCKS, 1024>>>();
    k_scatter<<<(E_EDGES + 255) / 256, 256>>>(ei);

    const int gemm1_blocks = ((N_NODES + 127) / 128) * 2;   // 1564
    const int gemmh_blocks = (N_NODES + 127) / 128;         // 782
    const int agg_blocks   = (N_NODES + 7) / 8;
    const int wprep_blocks = (D * D + 255) / 256;

    // Layer 1: x -> g_hh -> g_act
    k_wprep_bf16<<<wprep_blocks, 256>>>(W1);
    k_gemm_l1<<<gemm1_blocks, 256>>>(x);
    k_agg<false><<<agg_blocks, 256>>>(b1, nullptr);
    // Layer 2: g_act -> g_hh -> g_act
    k_wprep_f16<<<wprep_blocks, 256>>>(W2);
    k_gemm_h<<<gemmh_blocks, 256>>>();
    k_agg<false><<<agg_blocks, 256>>>(b2, nullptr);
    // Layer 3: g_act -> g_hh -> out
    k_wprep_f16<<<wprep_blocks, 256>>>(W3);
    k_gemm_h<<<gemmh_blocks, 256>>>();
    k_agg<true><<<agg_blocks, 256>>>(b3, out);
}

// round 10
// speedup vs baseline: 1.8253x; 1.0136x over previous
#include <cuda_runtime.h>
#include <cuda_bf16.h>
#include <cuda_fp16.h>

#define N_NODES 100000
#define D 128
#define E_EDGES 1600000
#define SCAN_BLOCKS ((N_NODES + 1023) / 1024)   // 98

// Scratch (device globals; no runtime allocation allowed)
__device__ __half g_hh[N_NODES * D];   // pre-normalized messages dinv*H, fp16
__device__ __half g_act[N_NODES * D];  // layer activations (fp16)
__device__ float g_dinv[N_NODES];
__device__ int   g_cnt[N_NODES];
__device__ int   g_rowptr[N_NODES + 1];
__device__ int   g_cursor[N_NODES];
__device__ int   g_csr_src[E_EDGES];
__device__ int   g_bsum[SCAN_BLOCKS];
__device__ int   g_boff[SCAN_BLOCKS];
__device__ __nv_bfloat16 g_wm1[D * D];  // W1^T main bf16 [n][k]
__device__ __nv_bfloat16 g_wr1[D * D];  // W1^T residual bf16
__device__ __half g_wm2[D * D], g_wr2[D * D];  // W2^T fp16 main/res
__device__ __half g_wm3[D * D], g_wr3[D * D];  // W3^T fp16 main/res

// ---------------------------------------------------------------------------
// Helpers
// ---------------------------------------------------------------------------
__device__ __forceinline__ void split2(float2 v, unsigned& m, unsigned& r) {
    __nv_bfloat16 mx = __float2bfloat16_rn(v.x);
    __nv_bfloat16 my = __float2bfloat16_rn(v.y);
    __nv_bfloat16 rx = __float2bfloat16_rn(v.x - __bfloat162float(mx));
    __nv_bfloat16 ry = __float2bfloat16_rn(v.y - __bfloat162float(my));
    m = (unsigned)__bfloat16_as_ushort(mx) | ((unsigned)__bfloat16_as_ushort(my) << 16);
    r = (unsigned)__bfloat16_as_ushort(rx) | ((unsigned)__bfloat16_as_ushort(ry) << 16);
}

__device__ __forceinline__ void mma_bf16(float* c, unsigned a0, unsigned a1,
                                         unsigned a2, unsigned a3,
                                         unsigned b0, unsigned b1) {
    asm volatile(
        "mma.sync.aligned.m16n8k16.row.col.f32.bf16.bf16.f32 "
        "{%0,%1,%2,%3}, {%4,%5,%6,%7}, {%8,%9}, {%0,%1,%2,%3};"
        : "+f"(c[0]), "+f"(c[1]), "+f"(c[2]), "+f"(c[3])
        : "r"(a0), "r"(a1), "r"(a2), "r"(a3), "r"(b0), "r"(b1));
}

__device__ __forceinline__ void mma_f16(float* c, unsigned a0, unsigned a1,
                                        unsigned a2, unsigned a3,
                                        unsigned b0, unsigned b1) {
    asm volatile(
        "mma.sync.aligned.m16n8k16.row.col.f32.f16.f16.f32 "
        "{%0,%1,%2,%3}, {%4,%5,%6,%7}, {%8,%9}, {%0,%1,%2,%3};"
        : "+f"(c[0]), "+f"(c[1]), "+f"(c[2]), "+f"(c[3])
        : "r"(a0), "r"(a1), "r"(a2), "r"(a3), "r"(b0), "r"(b1));
}

// ---------------------------------------------------------------------------
// CSR build: histogram -> parallel scan -> scatter
// ---------------------------------------------------------------------------
__global__ void k_zero_cnt() {
    int i = blockIdx.x * blockDim.x + threadIdx.x;
    if (i < N_NODES) g_cnt[i] = 0;
}

__global__ void k_count(const int* __restrict__ ei) {
    int e = blockIdx.x * blockDim.x + threadIdx.x;
    if (e < E_EDGES) atomicAdd(&g_cnt[ei[E_EDGES + e]], 1);
}

__global__ void __launch_bounds__(1024) k_scan_a() {
    __shared__ int sm[1024];
    int t = threadIdx.x;
    int i = blockIdx.x * 1024 + t;
    int v = (i < N_NODES) ? g_cnt[i] : 0;
    sm[t] = v;
    __syncthreads();
#pragma unroll
    for (int off = 1; off < 1024; off <<= 1) {
        int u = (t >= off) ? sm[t - off] : 0;
        __syncthreads();
        sm[t] += u;
        __syncthreads();
    }
    if (i < N_NODES) g_rowptr[i] = sm[t] - v;
    if (t == 1023) g_bsum[blockIdx.x] = sm[1023];
}

__global__ void __launch_bounds__(128) k_scan_b() {
    __shared__ int sm[128];
    int t = threadIdx.x;
    int v = (t < SCAN_BLOCKS) ? g_bsum[t] : 0;
    sm[t] = v;
    __syncthreads();
#pragma unroll
    for (int off = 1; off < 128; off <<= 1) {
        int u = (t >= off) ? sm[t - off] : 0;
        __syncthreads();
        sm[t] += u;
        __syncthreads();
    }
    if (t < SCAN_BLOCKS) g_boff[t] = sm[t] - v;
}

__global__ void __launch_bounds__(1024) k_scan_c() {
    int i = blockIdx.x * 1024 + threadIdx.x;
    if (i < N_NODES) {
        int r = g_rowptr[i] + g_boff[blockIdx.x];
        g_rowptr[i] = r;
        g_cursor[i] = r;
        g_dinv[i] = rsqrtf((float)g_cnt[i] + 1.0f);
    }
    if (i == 0) g_rowptr[N_NODES] = E_EDGES;
}

__global__ void k_scatter(const int* __restrict__ ei) {
    int e = blockIdx.x * blockDim.x + threadIdx.x;
    if (e < E_EDGES) {
        int src = ei[e];
        int dst = ei[E_EDGES + e];
        int pos = atomicAdd(&g_cursor[dst], 1);
        g_csr_src[pos] = src;
    }
}

// ---------------------------------------------------------------------------
// W prep (all 3 layers, one launch): split W^T into main+res, [n][k].
// ---------------------------------------------------------------------------
__global__ void k_wprep_all(const float* __restrict__ W1,
                            const float* __restrict__ W2,
                            const float* __restrict__ W3) {
    int t = blockIdx.x * 256 + threadIdx.x;
    int layer = t / (D * D);
    int idx   = t % (D * D);
    if (layer >= 3) return;
    int n = idx >> 7, k = idx & 127;
    if (layer == 0) {
        float w = W1[k * D + n];
        __nv_bfloat16 m = __float2bfloat16_rn(w);
        g_wm1[n * D + k] = m;
        g_wr1[n * D + k] = __float2bfloat16_rn(w - __bfloat162float(m));
    } else {
        const float* W = (layer == 1) ? W2 : W3;
        float w = W[k * D + n];
        __half m = __float2half_rn(w);
        __half r = __float2half_rn(w - __half2float(m));
        if (layer == 1) { g_wm2[n * D + k] = m; g_wr2[n * D + k] = r; }
        else            { g_wm3[n * D + k] = m; g_wr3[n * D + k] = r; }
    }
}

// ---------------------------------------------------------------------------
// Layer-1 GEMM: bf16 split-compensated (A from fp32 x), 3 MMA terms.
// 8 warps; warp tile 32x64; block M=128, FULL N=128 (X read once).
// Epilogue stores dinv[m]*(x@W) as fp16 into g_hh.
// ---------------------------------------------------------------------------
__global__ void __launch_bounds__(256)
k_gemm_l1(const float* __restrict__ X) {
    int tid  = threadIdx.x;
    int warp = tid >> 5, lane = tid & 31;
    int g  = lane >> 2;
    int tk = lane & 3;
    int m0 = blockIdx.x * 128 + (warp & 3) * 32;
    int n0 = (warp >> 2) * 64;

    float c[2][8][4];
#pragma unroll
    for (int t = 0; t < 2; ++t)
#pragma unroll
        for (int j = 0; j < 8; ++j)
#pragma unroll
            for (int q = 0; q < 4; ++q) c[t][j][q] = 0.0f;

#pragma unroll 1
    for (int kc = 0; kc < 8; ++kc) {
        int kb = kc * 16;

        unsigned am[2][4], ar[2][4];
#pragma unroll
        for (int t = 0; t < 2; ++t) {
            int r0 = m0 + t * 16 + g;
            int r1 = r0 + 8;
            float2 z = make_float2(0.f, 0.f);
            float2 x00 = (r0 < N_NODES) ? *(const float2*)&X[r0 * 128 + kb + tk * 2] : z;
            float2 x10 = (r1 < N_NODES) ? *(const float2*)&X[r1 * 128 + kb + tk * 2] : z;
            float2 x01 = (r0 < N_NODES) ? *(const float2*)&X[r0 * 128 + kb + 8 + tk * 2] : z;
            float2 x11 = (r1 < N_NODES) ? *(const float2*)&X[r1 * 128 + kb + 8 + tk * 2] : z;
            split2(x00, am[t][0], ar[t][0]);
            split2(x10, am[t][1], ar[t][1]);
            split2(x01, am[t][2], ar[t][2]);
            split2(x11, am[t][3], ar[t][3]);
        }

        unsigned bm[8][2], br[8][2];
#pragma unroll
        for (int j = 0; j < 8; ++j) {
            int n = n0 + j * 8 + g;
            int off = n * 128 + kb + tk * 2;
            bm[j][0] = *(const unsigned*)&g_wm1[off];
            bm[j][1] = *(const unsigned*)&g_wm1[off + 8];
            br[j][0] = *(const unsigned*)&g_wr1[off];
            br[j][1] = *(const unsigned*)&g_wr1[off + 8];
        }

#pragma unroll
        for (int t = 0; t < 2; ++t)
#pragma unroll
            for (int j = 0; j < 8; ++j) {
                mma_bf16(c[t][j], am[t][0], am[t][1], am[t][2], am[t][3],
                         bm[j][0], bm[j][1]);
                mma_bf16(c[t][j], ar[t][0], ar[t][1], ar[t][2], ar[t][3],
                         bm[j][0], bm[j][1]);
                mma_bf16(c[t][j], am[t][0], am[t][1], am[t][2], am[t][3],
                         br[j][0], br[j][1]);
            }
    }

#pragma unroll
    for (int t = 0; t < 2; ++t) {
        int r0 = m0 + t * 16 + g;
        int r1 = r0 + 8;
        float dv0 = (r0 < N_NODES) ? g_dinv[r0] : 0.f;
        float dv1 = (r1 < N_NODES) ? g_dinv[r1] : 0.f;
#pragma unroll
        for (int j = 0; j < 8; ++j) {
            int col = n0 + j * 8 + tk * 2;
            if (r0 < N_NODES)
                *(__half2*)&g_hh[r0 * 128 + col] =
                    __floats2half2_rn(dv0 * c[t][j][0], dv0 * c[t][j][1]);
            if (r1 < N_NODES)
                *(__half2*)&g_hh[r1 * 128 + col] =
                    __floats2half2_rn(dv1 * c[t][j][2], dv1 * c[t][j][3]);
        }
    }
}

// ---------------------------------------------------------------------------
// Layers 2/3 GEMM: A fp16-exact from g_act, W fp16 main+res, 2 MMA terms.
// 8 warps; warp tile 32x64; block M=128, full N=128. LAYER selects weights.
// ---------------------------------------------------------------------------
template <int LAYER>
__global__ void __launch_bounds__(256)
k_gemm_h() {
    const __half* Wm = (LAYER == 2) ? g_wm2 : g_wm3;
    const __half* Wr = (LAYER == 2) ? g_wr2 : g_wr3;
    int tid  = threadIdx.x;
    int warp = tid >> 5, lane = tid & 31;
    int g  = lane >> 2;
    int tk = lane & 3;
    int m0 = blockIdx.x * 128 + (warp & 3) * 32;
    int n0 = (warp >> 2) * 64;

    float c[2][8][4];
#pragma unroll
    for (int t = 0; t < 2; ++t)
#pragma unroll
        for (int j = 0; j < 8; ++j)
#pragma unroll
            for (int q = 0; q < 4; ++q) c[t][j][q] = 0.0f;

#pragma unroll 1
    for (int kc = 0; kc < 8; ++kc) {
        int kb = kc * 16;

        unsigned a[2][4];
#pragma unroll
        for (int t = 0; t < 2; ++t) {
            int r0 = m0 + t * 16 + g;
            int r1 = r0 + 8;
            a[t][0] = (r0 < N_NODES) ? *(const unsigned*)&g_act[r0 * 128 + kb + tk * 2] : 0u;
            a[t][1] = (r1 < N_NODES) ? *(const unsigned*)&g_act[r1 * 128 + kb + tk * 2] : 0u;
            a[t][2] = (r0 < N_NODES) ? *(const unsigned*)&g_act[r0 * 128 + kb + 8 + tk * 2] : 0u;
            a[t][3] = (r1 < N_NODES) ? *(const unsigned*)&g_act[r1 * 128 + kb + 8 + tk * 2] : 0u;
        }

        unsigned bm[8][2], br[8][2];
#pragma unroll
        for (int j = 0; j < 8; ++j) {
            int n = n0 + j * 8 + g;
            int off = n * 128 + kb + tk * 2;
            bm[j][0] = *(const unsigned*)&Wm[off];
            bm[j][1] = *(const unsigned*)&Wm[off + 8];
            br[j][0] = *(const unsigned*)&Wr[off];
            br[j][1] = *(const unsigned*)&Wr[off + 8];
        }

#pragma unroll
        for (int t = 0; t < 2; ++t)
#pragma unroll
            for (int j = 0; j < 8; ++j) {
                mma_f16(c[t][j], a[t][0], a[t][1], a[t][2], a[t][3],
                        bm[j][0], bm[j][1]);
                mma_f16(c[t][j], a[t][0], a[t][1], a[t][2], a[t][3],
                        br[j][0], br[j][1]);
            }
    }

#pragma unroll
    for (int t = 0; t < 2; ++t) {
        int r0 = m0 + t * 16 + g;
        int r1 = r0 + 8;
        float dv0 = (r0 < N_NODES) ? g_dinv[r0] : 0.f;
        float dv1 = (r1 < N_NODES) ? g_dinv[r1] : 0.f;
#pragma unroll
        for (int j = 0; j < 8; ++j) {
            int col = n0 + j * 8 + tk * 2;
            if (r0 < N_NODES)
                *(__half2*)&g_hh[r0 * 128 + col] =
                    __floats2half2_rn(dv0 * c[t][j][0], dv0 * c[t][j][1]);
            if (r1 < N_NODES)
                *(__half2*)&g_hh[r1 * 128 + col] =
                    __floats2half2_rn(dv1 * c[t][j][2], dv1 * c[t][j][3]);
        }
    }
}

// ---------------------------------------------------------------------------
// Aggregation: 16 lanes per dst node (2 nodes/warp); lane owns 8 halves
// (one uint4, 16B) of the 256B row. Neighbor rows fetched with LDG.128.
// out[dst] = relu( dinv[dst] * ( sum_src H'[src] + H'[dst] ) + b ).
// ---------------------------------------------------------------------------
template <bool TO_OUT>
__global__ void __launch_bounds__(256)
k_agg(const float* __restrict__ b, float* __restrict__ OUT) {
    int node = blockIdx.x * 16 + (threadIdx.x >> 4);
    int lane16 = threadIdx.x & 15;
    if (node >= N_NODES) return;

    const uint4* Hv = (const uint4*)g_hh;   // 16 x 16B per 128-half row

    float dv = g_dinv[node];
    float acc[8];
    {
        uint4 raw = Hv[node * 16 + lane16];
        float2 q0 = __half22float2(*(__half2*)&raw.x);
        float2 q1 = __half22float2(*(__half2*)&raw.y);
        float2 q2 = __half22float2(*(__half2*)&raw.z);
        float2 q3 = __half22float2(*(__half2*)&raw.w);
        acc[0] = q0.x; acc[1] = q0.y; acc[2] = q1.x; acc[3] = q1.y;
        acc[4] = q2.x; acc[5] = q2.y; acc[6] = q3.x; acc[7] = q3.y;
    }

    int j = g_rowptr[node];
    int end = g_rowptr[node + 1];

    while (j < end) {
        int take = end - j;
        if (take > 16) take = 16;
        int sidx = (lane16 < take) ? g_csr_src[j + lane16] : 0;
#pragma unroll 4
        for (int t = 0; t < take; ++t) {
            int s = __shfl_sync(0xffffffffu, sidx, t, 16);
            uint4 raw = Hv[s * 16 + lane16];
            float2 q0 = __half22float2(*(__half2*)&raw.x);
            float2 q1 = __half22float2(*(__half2*)&raw.y);
            float2 q2 = __half22float2(*(__half2*)&raw.z);
            float2 q3 = __half22float2(*(__half2*)&raw.w);
            acc[0] += q0.x; acc[1] += q0.y; acc[2] += q1.x; acc[3] += q1.y;
            acc[4] += q2.x; acc[5] += q2.y; acc[6] += q3.x; acc[7] += q3.y;
        }
        j += take;
    }

    float4 bb0 = *(const float4*)&b[lane16 * 8];
    float4 bb1 = *(const float4*)&b[lane16 * 8 + 4];
    float o[8];
    o[0] = fmaxf(fmaf(dv, acc[0], bb0.x), 0.f);
    o[1] = fmaxf(fmaf(dv, acc[1], bb0.y), 0.f);
    o[2] = fmaxf(fmaf(dv, acc[2], bb0.z), 0.f);
    o[3] = fmaxf(fmaf(dv, acc[3], bb0.w), 0.f);
    o[4] = fmaxf(fmaf(dv, acc[4], bb1.x), 0.f);
    o[5] = fmaxf(fmaf(dv, acc[5], bb1.y), 0.f);
    o[6] = fmaxf(fmaf(dv, acc[6], bb1.z), 0.f);
    o[7] = fmaxf(fmaf(dv, acc[7], bb1.w), 0.f);

    if (TO_OUT) {
        ((float4*)OUT)[node * 32 + lane16 * 2]     = make_float4(o[0], o[1], o[2], o[3]);
        ((float4*)OUT)[node * 32 + lane16 * 2 + 1] = make_float4(o[4], o[5], o[6], o[7]);
    } else {
        uint4 w;
        *(__half2*)&w.x = __floats2half2_rn(o[0], o[1]);
        *(__half2*)&w.y = __floats2half2_rn(o[2], o[3]);
        *(__half2*)&w.z = __floats2half2_rn(o[4], o[5]);
        *(__half2*)&w.w = __floats2half2_rn(o[6], o[7]);
        ((uint4*)g_act)[node * 16 + lane16] = w;
    }
}

// ---------------------------------------------------------------------------
extern "C" void kernel_launch(void* const* d_in, const int* in_sizes, int n_in,
                              void* d_out, int out_size) {
    const float* x  = (const float*)d_in[0];
    const int*   ei = (const int*)d_in[1];
    const float* W1 = (const float*)d_in[2];
    const float* b1 = (const float*)d_in[3];
    const float* W2 = (const float*)d_in[4];
    const float* b2 = (const float*)d_in[5];
    const float* W3 = (const float*)d_in[6];
    const float* b3 = (const float*)d_in[7];
    float* out = (float*)d_out;

    // W prep for all layers (single launch, off critical path)
    k_wprep_all<<<(3 * D * D + 255) / 256, 256>>>(W1, W2, W3);

    // CSR build (dinv needed by GEMM epilogue)
    k_zero_cnt<<<(N_NODES + 255) / 256, 256>>>();
    k_count<<<(E_EDGES + 255) / 256, 256>>>(ei);
    k_scan_a<<<SCAN_BLOCKS, 1024>>>();
    k_scan_b<<<1, 128>>>();
    k_scan_c<<<SCAN_BLOCKS, 1024>>>();
    k_scatter<<<(E_EDGES + 255) / 256, 256>>>(ei);

    const int gemm_blocks = (N_NODES + 127) / 128;          // 782
    const int agg_blocks  = (N_NODES + 15) / 16;            // 6250

    // Layer 1: x -> g_hh -> g_act
    k_gemm_l1<<<gemm_blocks, 256>>>(x);
    k_agg<false><<<agg_blocks, 256>>>(b1, nullptr);
    // Layer 2: g_act -> g_hh -> g_act
    k_gemm_h<2><<<gemm_blocks, 256>>>();
    k_agg<false><<<agg_blocks, 256>>>(b2, nullptr);
    // Layer 3: g_act -> g_hh -> out
    k_gemm_h<3><<<gemm_blocks, 256>>>();
    k_agg<true><<<agg_blocks, 256>>>(b3, out);
}

// round 11
// speedup vs baseline: 2.5023x; 1.3709x over previous
#include <cuda_runtime.h>
#include <cuda_bf16.h>
#include <cuda_fp16.h>

#define N_NODES 100000
#define D 128
#define E_EDGES 1600000
#define SCAN_BLOCKS ((N_NODES + 1023) / 1024)   // 98

// Scratch (device globals; no runtime allocation allowed)
__device__ __half g_hh[N_NODES * D];   // pre-normalized messages dinv*H, fp16
__device__ __half g_act[N_NODES * D];  // activations, fp16, FRAGMENT-PERMUTED rows
__device__ float g_dinv[N_NODES];
__device__ int   g_cnt[N_NODES];
__device__ int   g_rowptr[N_NODES + 1];
__device__ int   g_cursor[N_NODES];
__device__ int   g_csr_src[E_EDGES];
__device__ int   g_bsum[SCAN_BLOCKS];
__device__ int   g_boff[SCAN_BLOCKS];
// Fragment-packed W: [kc][n][tk] -> uint4 {bm0, bm1, br0, br1}
__device__ uint4 g_wpk1[8 * D * 4];   // layer 1, bf16 main/res
__device__ uint4 g_wpk2[8 * D * 4];   // layer 2, fp16 main/res
__device__ uint4 g_wpk3[8 * D * 4];   // layer 3, fp16 main/res

// ---------------------------------------------------------------------------
// Helpers
// ---------------------------------------------------------------------------
__device__ __forceinline__ void split2(float2 v, unsigned& m, unsigned& r) {
    __nv_bfloat16 mx = __float2bfloat16_rn(v.x);
    __nv_bfloat16 my = __float2bfloat16_rn(v.y);
    __nv_bfloat16 rx = __float2bfloat16_rn(v.x - __bfloat162float(mx));
    __nv_bfloat16 ry = __float2bfloat16_rn(v.y - __bfloat162float(my));
    m = (unsigned)__bfloat16_as_ushort(mx) | ((unsigned)__bfloat16_as_ushort(my) << 16);
    r = (unsigned)__bfloat16_as_ushort(rx) | ((unsigned)__bfloat16_as_ushort(ry) << 16);
}

__device__ __forceinline__ void mma_bf16(float* c, unsigned a0, unsigned a1,
                                         unsigned a2, unsigned a3,
                                         unsigned b0, unsigned b1) {
    asm volatile(
        "mma.sync.aligned.m16n8k16.row.col.f32.bf16.bf16.f32 "
        "{%0,%1,%2,%3}, {%4,%5,%6,%7}, {%8,%9}, {%0,%1,%2,%3};"
        : "+f"(c[0]), "+f"(c[1]), "+f"(c[2]), "+f"(c[3])
        : "r"(a0), "r"(a1), "r"(a2), "r"(a3), "r"(b0), "r"(b1));
}

__device__ __forceinline__ void mma_f16(float* c, unsigned a0, unsigned a1,
                                        unsigned a2, unsigned a3,
                                        unsigned b0, unsigned b1) {
    asm volatile(
        "mma.sync.aligned.m16n8k16.row.col.f32.f16.f16.f32 "
        "{%0,%1,%2,%3}, {%4,%5,%6,%7}, {%8,%9}, {%0,%1,%2,%3};"
        : "+f"(c[0]), "+f"(c[1]), "+f"(c[2]), "+f"(c[3])
        : "r"(a0), "r"(a1), "r"(a2), "r"(a3), "r"(b0), "r"(b1));
}

// ---------------------------------------------------------------------------
// CSR build: histogram -> parallel scan -> scatter
// ---------------------------------------------------------------------------
__global__ void k_zero_cnt() {
    int i = blockIdx.x * blockDim.x + threadIdx.x;
    if (i < N_NODES) g_cnt[i] = 0;
}

__global__ void k_count(const int* __restrict__ ei) {
    int e = blockIdx.x * blockDim.x + threadIdx.x;
    if (e < E_EDGES) atomicAdd(&g_cnt[ei[E_EDGES + e]], 1);
}

__global__ void __launch_bounds__(1024) k_scan_a() {
    __shared__ int sm[1024];
    int t = threadIdx.x;
    int i = blockIdx.x * 1024 + t;
    int v = (i < N_NODES) ? g_cnt[i] : 0;
    sm[t] = v;
    __syncthreads();
#pragma unroll
    for (int off = 1; off < 1024; off <<= 1) {
        int u = (t >= off) ? sm[t - off] : 0;
        __syncthreads();
        sm[t] += u;
        __syncthreads();
    }
    if (i < N_NODES) g_rowptr[i] = sm[t] - v;
    if (t == 1023) g_bsum[blockIdx.x] = sm[1023];
}

__global__ void __launch_bounds__(128) k_scan_b() {
    __shared__ int sm[128];
    int t = threadIdx.x;
    int v = (t < SCAN_BLOCKS) ? g_bsum[t] : 0;
    sm[t] = v;
    __syncthreads();
#pragma unroll
    for (int off = 1; off < 128; off <<= 1) {
        int u = (t >= off) ? sm[t - off] : 0;
        __syncthreads();
        sm[t] += u;
        __syncthreads();
    }
    if (t < SCAN_BLOCKS) g_boff[t] = sm[t] - v;
}

__global__ void __launch_bounds__(1024) k_scan_c() {
    int i = blockIdx.x * 1024 + threadIdx.x;
    if (i < N_NODES) {
        int r = g_rowptr[i] + g_boff[blockIdx.x];
        g_rowptr[i] = r;
        g_cursor[i] = r;
        g_dinv[i] = rsqrtf((float)g_cnt[i] + 1.0f);
    }
    if (i == 0) g_rowptr[N_NODES] = E_EDGES;
}

__global__ void k_scatter(const int* __restrict__ ei) {
    int e = blockIdx.x * blockDim.x + threadIdx.x;
    if (e < E_EDGES) {
        int src = ei[e];
        int dst = ei[E_EDGES + e];
        int pos = atomicAdd(&g_cursor[dst], 1);
        g_csr_src[pos] = src;
    }
}

// ---------------------------------------------------------------------------
// W prep: fragment-packed. One thread per (layer, kc, n, tk).
// k0 = 16*kc + 2*tk (pair), k1 = k0 + 8 (pair). uint4 = {m(k0),m(k1),r(k0),r(k1)}
// ---------------------------------------------------------------------------
__global__ void k_wprep_all(const float* __restrict__ W1,
                            const float* __restrict__ W2,
                            const float* __restrict__ W3) {
    int t = blockIdx.x * 256 + threadIdx.x;
    if (t >= 3 * 8 * D * 4) return;
    int layer = t / (8 * D * 4);
    int idx   = t % (8 * D * 4);
    int kc = idx >> 9;            // /(128*4)
    int n  = (idx >> 2) & 127;
    int tk = idx & 3;
    int k0 = kc * 16 + tk * 2;
    int k1 = k0 + 8;

    const float* W = (layer == 0) ? W1 : (layer == 1) ? W2 : W3;
    float w00 = W[k0 * D + n],       w01 = W[(k0 + 1) * D + n];
    float w10 = W[k1 * D + n],       w11 = W[(k1 + 1) * D + n];

    uint4 p;
    if (layer == 0) {
        unsigned m0, r0, m1, r1;
        split2(make_float2(w00, w01), m0, r0);
        split2(make_float2(w10, w11), m1, r1);
        p = make_uint4(m0, m1, r0, r1);
        g_wpk1[idx] = p;
    } else {
        __half2 m0 = __floats2half2_rn(w00, w01);
        __half2 r0 = __floats2half2_rn(w00 - __half2float(__low2half(m0)),
                                       w01 - __half2float(__high2half(m0)));
        __half2 m1 = __floats2half2_rn(w10, w11);
        __half2 r1 = __floats2half2_rn(w10 - __half2float(__low2half(m1)),
                                       w11 - __half2float(__high2half(m1)));
        p = make_uint4(*(unsigned*)&m0, *(unsigned*)&m1,
                       *(unsigned*)&r0, *(unsigned*)&r1);
        if (layer == 1) g_wpk2[idx] = p; else g_wpk3[idx] = p;
    }
}

// ---------------------------------------------------------------------------
// Layer-1 GEMM: bf16 split-compensated (A from fp32 x), 3 MMA terms.
// 8 warps; warp tile 32x64; block M=128, full N=128. Packed W fragments.
// ---------------------------------------------------------------------------
__global__ void __launch_bounds__(256)
k_gemm_l1(const float* __restrict__ X) {
    int tid  = threadIdx.x;
    int warp = tid >> 5, lane = tid & 31;
    int g  = lane >> 2;
    int tk = lane & 3;
    int m0 = blockIdx.x * 128 + (warp & 3) * 32;
    int n0 = (warp >> 2) * 64;

    float c[2][8][4];
#pragma unroll
    for (int t = 0; t < 2; ++t)
#pragma unroll
        for (int j = 0; j < 8; ++j)
#pragma unroll
            for (int q = 0; q < 4; ++q) c[t][j][q] = 0.0f;

#pragma unroll 1
    for (int kc = 0; kc < 8; ++kc) {
        int kb = kc * 16;

        unsigned am[2][4], ar[2][4];
#pragma unroll
        for (int t = 0; t < 2; ++t) {
            int r0 = m0 + t * 16 + g;
            int r1 = r0 + 8;
            float2 z = make_float2(0.f, 0.f);
            float2 x00 = (r0 < N_NODES) ? *(const float2*)&X[r0 * 128 + kb + tk * 2] : z;
            float2 x10 = (r1 < N_NODES) ? *(const float2*)&X[r1 * 128 + kb + tk * 2] : z;
            float2 x01 = (r0 < N_NODES) ? *(const float2*)&X[r0 * 128 + kb + 8 + tk * 2] : z;
            float2 x11 = (r1 < N_NODES) ? *(const float2*)&X[r1 * 128 + kb + 8 + tk * 2] : z;
            split2(x00, am[t][0], ar[t][0]);
            split2(x10, am[t][1], ar[t][1]);
            split2(x01, am[t][2], ar[t][2]);
            split2(x11, am[t][3], ar[t][3]);
        }

        unsigned bm[8][2], br[8][2];
#pragma unroll
        for (int j = 0; j < 8; ++j) {
            uint4 w = g_wpk1[((kc * 128 + n0 + j * 8 + g) << 2) + tk];
            bm[j][0] = w.x; bm[j][1] = w.y; br[j][0] = w.z; br[j][1] = w.w;
        }

#pragma unroll
        for (int t = 0; t < 2; ++t)
#pragma unroll
            for (int j = 0; j < 8; ++j) {
                mma_bf16(c[t][j], am[t][0], am[t][1], am[t][2], am[t][3],
                         bm[j][0], bm[j][1]);
                mma_bf16(c[t][j], ar[t][0], ar[t][1], ar[t][2], ar[t][3],
                         bm[j][0], bm[j][1]);
                mma_bf16(c[t][j], am[t][0], am[t][1], am[t][2], am[t][3],
                         br[j][0], br[j][1]);
            }
    }

#pragma unroll
    for (int t = 0; t < 2; ++t) {
        int r0 = m0 + t * 16 + g;
        int r1 = r0 + 8;
        float dv0 = (r0 < N_NODES) ? g_dinv[r0] : 0.f;
        float dv1 = (r1 < N_NODES) ? g_dinv[r1] : 0.f;
#pragma unroll
        for (int j = 0; j < 8; ++j) {
            int col = n0 + j * 8 + tk * 2;
            if (r0 < N_NODES)
                *(__half2*)&g_hh[r0 * 128 + col] =
                    __floats2half2_rn(dv0 * c[t][j][0], dv0 * c[t][j][1]);
            if (r1 < N_NODES)
                *(__half2*)&g_hh[r1 * 128 + col] =
                    __floats2half2_rn(dv1 * c[t][j][2], dv1 * c[t][j][3]);
        }
    }
}

// ---------------------------------------------------------------------------
// Layers 2/3 GEMM: A fp16-exact from permuted g_act (one LDG.64 per row/kc),
// packed W fragments (one LDG.128 per j/kc), 2 MMA terms.
// ---------------------------------------------------------------------------
template <int LAYER>
__global__ void __launch_bounds__(256)
k_gemm_h() {
    const uint4* Wp = (LAYER == 2) ? g_wpk2 : g_wpk3;
    int tid  = threadIdx.x;
    int warp = tid >> 5, lane = tid & 31;
    int g  = lane >> 2;
    int tk = lane & 3;
    int m0 = blockIdx.x * 128 + (warp & 3) * 32;
    int n0 = (warp >> 2) * 64;

    const uint2* A = (const uint2*)g_act;   // permuted rows: uint2 idx r*32+kc*4+tk

    float c[2][8][4];
#pragma unroll
    for (int t = 0; t < 2; ++t)
#pragma unroll
        for (int j = 0; j < 8; ++j)
#pragma unroll
            for (int q = 0; q < 4; ++q) c[t][j][q] = 0.0f;

#pragma unroll 1
    for (int kc = 0; kc < 8; ++kc) {
        unsigned a[2][4];
#pragma unroll
        for (int t = 0; t < 2; ++t) {
            int r0 = m0 + t * 16 + g;
            int r1 = r0 + 8;
            uint2 z = make_uint2(0u, 0u);
            uint2 v0 = (r0 < N_NODES) ? A[r0 * 32 + kc * 4 + tk] : z;
            uint2 v1 = (r1 < N_NODES) ? A[r1 * 32 + kc * 4 + tk] : z;
            a[t][0] = v0.x; a[t][2] = v0.y;
            a[t][1] = v1.x; a[t][3] = v1.y;
        }

        unsigned bm[8][2], br[8][2];
#pragma unroll
        for (int j = 0; j < 8; ++j) {
            uint4 w = Wp[((kc * 128 + n0 + j * 8 + g) << 2) + tk];
            bm[j][0] = w.x; bm[j][1] = w.y; br[j][0] = w.z; br[j][1] = w.w;
        }

#pragma unroll
        for (int t = 0; t < 2; ++t)
#pragma unroll
            for (int j = 0; j < 8; ++j) {
                mma_f16(c[t][j], a[t][0], a[t][1], a[t][2], a[t][3],
                        bm[j][0], bm[j][1]);
                mma_f16(c[t][j], a[t][0], a[t][1], a[t][2], a[t][3],
                        br[j][0], br[j][1]);
            }
    }

#pragma unroll
    for (int t = 0; t < 2; ++t) {
        int r0 = m0 + t * 16 + g;
        int r1 = r0 + 8;
        float dv0 = (r0 < N_NODES) ? g_dinv[r0] : 0.f;
        float dv1 = (r1 < N_NODES) ? g_dinv[r1] : 0.f;
#pragma unroll
        for (int j = 0; j < 8; ++j) {
            int col = n0 + j * 8 + tk * 2;
            if (r0 < N_NODES)
                *(__half2*)&g_hh[r0 * 128 + col] =
                    __floats2half2_rn(dv0 * c[t][j][0], dv0 * c[t][j][1]);
            if (r1 < N_NODES)
                *(__half2*)&g_hh[r1 * 128 + col] =
                    __floats2half2_rn(dv1 * c[t][j][2], dv1 * c[t][j][3]);
        }
    }
}

// ---------------------------------------------------------------------------
// Aggregation: 16 lanes per dst node; lane owns 8 halves (uint4) of the row.
// out = relu( dinv[dst] * ( sum_src H'[src] + H'[dst] ) + b ).
// TO_OUT=false -> writes g_act in FRAGMENT-PERMUTED order (4 STG.32).
// ---------------------------------------------------------------------------
template <bool TO_OUT>
__global__ void __launch_bounds__(256)
k_agg(const float* __restrict__ b, float* __restrict__ OUT) {
    int node = blockIdx.x * 16 + (threadIdx.x >> 4);
    int lane16 = threadIdx.x & 15;
    if (node >= N_NODES) return;

    const uint4* Hv = (const uint4*)g_hh;

    float dv = g_dinv[node];
    float acc[8];
    {
        uint4 raw = Hv[node * 16 + lane16];
        float2 q0 = __half22float2(*(__half2*)&raw.x);
        float2 q1 = __half22float2(*(__half2*)&raw.y);
        float2 q2 = __half22float2(*(__half2*)&raw.z);
        float2 q3 = __half22float2(*(__half2*)&raw.w);
        acc[0] = q0.x; acc[1] = q0.y; acc[2] = q1.x; acc[3] = q1.y;
        acc[4] = q2.x; acc[5] = q2.y; acc[6] = q3.x; acc[7] = q3.y;
    }

    int j = g_rowptr[node];
    int end = g_rowptr[node + 1];

    while (j < end) {
        int take = end - j;
        if (take > 16) take = 16;
        int sidx = (lane16 < take) ? g_csr_src[j + lane16] : 0;
#pragma unroll 4
        for (int t = 0; t < take; ++t) {
            int s = __shfl_sync(0xffffffffu, sidx, t, 16);
            uint4 raw = Hv[s * 16 + lane16];
            float2 q0 = __half22float2(*(__half2*)&raw.x);
            float2 q1 = __half22float2(*(__half2*)&raw.y);
            float2 q2 = __half22float2(*(__half2*)&raw.z);
            float2 q3 = __half22float2(*(__half2*)&raw.w);
            acc[0] += q0.x; acc[1] += q0.y; acc[2] += q1.x; acc[3] += q1.y;
            acc[4] += q2.x; acc[5] += q2.y; acc[6] += q3.x; acc[7] += q3.y;
        }
        j += take;
    }

    float4 bb0 = *(const float4*)&b[lane16 * 8];
    float4 bb1 = *(const float4*)&b[lane16 * 8 + 4];
    float o[8];
    o[0] = fmaxf(fmaf(dv, acc[0], bb0.x), 0.f);
    o[1] = fmaxf(fmaf(dv, acc[1], bb0.y), 0.f);
    o[2] = fmaxf(fmaf(dv, acc[2], bb0.z), 0.f);
    o[3] = fmaxf(fmaf(dv, acc[3], bb0.w), 0.f);
    o[4] = fmaxf(fmaf(dv, acc[4], bb1.x), 0.f);
    o[5] = fmaxf(fmaf(dv, acc[5], bb1.y), 0.f);
    o[6] = fmaxf(fmaf(dv, acc[6], bb1.z), 0.f);
    o[7] = fmaxf(fmaf(dv, acc[7], bb1.w), 0.f);

    if (TO_OUT) {
        ((float4*)OUT)[node * 32 + lane16 * 2]     = make_float4(o[0], o[1], o[2], o[3]);
        ((float4*)OUT)[node * 32 + lane16 * 2 + 1] = make_float4(o[4], o[5], o[6], o[7]);
    } else {
        // Permuted store: chunk c = lane16>>1; even lane -> uints 8c+{0,2,4,6},
        // odd lane -> 8c+{1,3,5,7}. (Within-chunk fragment order for gemm_h.)
        int cch = lane16 >> 1;
        int odd = lane16 & 1;
        unsigned* dst = (unsigned*)g_act + node * 64 + cch * 8 + odd;
        __half2 h0 = __floats2half2_rn(o[0], o[1]);
        __half2 h1 = __floats2half2_rn(o[2], o[3]);
        __half2 h2 = __floats2half2_rn(o[4], o[5]);
        __half2 h3 = __floats2half2_rn(o[6], o[7]);
        dst[0] = *(unsigned*)&h0;
        dst[2] = *(unsigned*)&h1;
        dst[4] = *(unsigned*)&h2;
        dst[6] = *(unsigned*)&h3;
    }
}

// ---------------------------------------------------------------------------
extern "C" void kernel_launch(void* const* d_in, const int* in_sizes, int n_in,
                              void* d_out, int out_size) {
    const float* x  = (const float*)d_in[0];
    const int*   ei = (const int*)d_in[1];
    const float* W1 = (const float*)d_in[2];
    const float* b1 = (const float*)d_in[3];
    const float* W2 = (const float*)d_in[4];
    const float* b2 = (const float*)d_in[5];
    const float* W3 = (const float*)d_in[6];
    const float* b3 = (const float*)d_in[7];
    float* out = (float*)d_out;

    // W prep for all layers (single launch)
    k_wprep_all<<<(3 * 8 * D * 4 + 255) / 256, 256>>>(W1, W2, W3);

    // CSR build (dinv needed by GEMM epilogue)
    k_zero_cnt<<<(N_NODES + 255) / 256, 256>>>();
    k_count<<<(E_EDGES + 255) / 256, 256>>>(ei);
    k_scan_a<<<SCAN_BLOCKS, 1024>>>();
    k_scan_b<<<1, 128>>>();
    k_scan_c<<<SCAN_BLOCKS, 1024>>>();
    k_scatter<<<(E_EDGES + 255) / 256, 256>>>(ei);

    const int gemm_blocks = (N_NODES + 127) / 128;          // 782
    const int agg_blocks  = (N_NODES + 15) / 16;            // 6250

    // Layer 1: x -> g_hh -> g_act (permuted)
    k_gemm_l1<<<gemm_blocks, 256>>>(x);
    k_agg<false><<<agg_blocks, 256>>>(b1, nullptr);
    // Layer 2: g_act -> g_hh -> g_act
    k_gemm_h<2><<<gemm_blocks, 256>>>();
    k_agg<false><<<agg_blocks, 256>>>(b2, nullptr);
    // Layer 3: g_act -> g_hh -> out (fp32, unpermuted)
    k_gemm_h<3><<<gemm_blocks, 256>>>();
    k_agg<true><<<agg_blocks, 256>>>(b3, out);
}

// round 12
// speedup vs baseline: 2.6342x; 1.0527x over previous
#include <cuda_runtime.h>
#include <cuda_bf16.h>
#include <cuda_fp16.h>

#define N_NODES 100000
#define D 128
#define E_EDGES 1600000
#define SCAN_BLOCKS ((N_NODES + 1023) / 1024)   // 98

// Scratch (device globals; no runtime allocation allowed)
__device__ __half g_hh[N_NODES * D];   // pre-normalized messages dinv*H, fp16
__device__ __half g_act[N_NODES * D];  // activations, fp16, FRAGMENT-PERMUTED rows
__device__ float g_dinv[N_NODES];
__device__ int   g_cnt[N_NODES];
__device__ int   g_rowptr[N_NODES + 1];
__device__ int   g_cursor[N_NODES];
__device__ int   g_csr_src[E_EDGES];
__device__ int   g_bsum[SCAN_BLOCKS];
__device__ int   g_boff[SCAN_BLOCKS];
// Layer-1 fragment-packed W (bf16 main+res): [kc][n][tk] -> {bm0,bm1,br0,br1}
__device__ uint4 g_wpk1[8 * D * 4];
// Layers 2/3 fragment-packed W (fp16 main only): [kc][n][tk] -> {bm0,bm1}
__device__ uint2 g_wpk2[8 * D * 4];
__device__ uint2 g_wpk3[8 * D * 4];

// ---------------------------------------------------------------------------
// Helpers
// ---------------------------------------------------------------------------
__device__ __forceinline__ void split2(float2 v, unsigned& m, unsigned& r) {
    __nv_bfloat16 mx = __float2bfloat16_rn(v.x);
    __nv_bfloat16 my = __float2bfloat16_rn(v.y);
    __nv_bfloat16 rx = __float2bfloat16_rn(v.x - __bfloat162float(mx));
    __nv_bfloat16 ry = __float2bfloat16_rn(v.y - __bfloat162float(my));
    m = (unsigned)__bfloat16_as_ushort(mx) | ((unsigned)__bfloat16_as_ushort(my) << 16);
    r = (unsigned)__bfloat16_as_ushort(rx) | ((unsigned)__bfloat16_as_ushort(ry) << 16);
}

__device__ __forceinline__ void mma_bf16(float* c, unsigned a0, unsigned a1,
                                         unsigned a2, unsigned a3,
                                         unsigned b0, unsigned b1) {
    asm volatile(
        "mma.sync.aligned.m16n8k16.row.col.f32.bf16.bf16.f32 "
        "{%0,%1,%2,%3}, {%4,%5,%6,%7}, {%8,%9}, {%0,%1,%2,%3};"
        : "+f"(c[0]), "+f"(c[1]), "+f"(c[2]), "+f"(c[3])
        : "r"(a0), "r"(a1), "r"(a2), "r"(a3), "r"(b0), "r"(b1));
}

__device__ __forceinline__ void mma_f16(float* c, unsigned a0, unsigned a1,
                                        unsigned a2, unsigned a3,
                                        unsigned b0, unsigned b1) {
    asm volatile(
        "mma.sync.aligned.m16n8k16.row.col.f32.f16.f16.f32 "
        "{%0,%1,%2,%3}, {%4,%5,%6,%7}, {%8,%9}, {%0,%1,%2,%3};"
        : "+f"(c[0]), "+f"(c[1]), "+f"(c[2]), "+f"(c[3])
        : "r"(a0), "r"(a1), "r"(a2), "r"(a3), "r"(b0), "r"(b1));
}

// ---------------------------------------------------------------------------
// CSR build: histogram -> parallel scan -> scatter (4 edges/thread)
// ---------------------------------------------------------------------------
__global__ void k_zero_cnt() {
    int i = blockIdx.x * blockDim.x + threadIdx.x;
    if (i < N_NODES) g_cnt[i] = 0;
}

__global__ void k_count(const int* __restrict__ ei) {
    int e4 = blockIdx.x * blockDim.x + threadIdx.x;
    if (e4 < E_EDGES / 4) {
        int4 d = ((const int4*)(ei + E_EDGES))[e4];
        atomicAdd(&g_cnt[d.x], 1);
        atomicAdd(&g_cnt[d.y], 1);
        atomicAdd(&g_cnt[d.z], 1);
        atomicAdd(&g_cnt[d.w], 1);
    }
}

__global__ void __launch_bounds__(1024) k_scan_a() {
    __shared__ int sm[1024];
    int t = threadIdx.x;
    int i = blockIdx.x * 1024 + t;
    int v = (i < N_NODES) ? g_cnt[i] : 0;
    sm[t] = v;
    __syncthreads();
#pragma unroll
    for (int off = 1; off < 1024; off <<= 1) {
        int u = (t >= off) ? sm[t - off] : 0;
        __syncthreads();
        sm[t] += u;
        __syncthreads();
    }
    if (i < N_NODES) g_rowptr[i] = sm[t] - v;
    if (t == 1023) g_bsum[blockIdx.x] = sm[1023];
}

__global__ void __launch_bounds__(128) k_scan_b() {
    __shared__ int sm[128];
    int t = threadIdx.x;
    int v = (t < SCAN_BLOCKS) ? g_bsum[t] : 0;
    sm[t] = v;
    __syncthreads();
#pragma unroll
    for (int off = 1; off < 128; off <<= 1) {
        int u = (t >= off) ? sm[t - off] : 0;
        __syncthreads();
        sm[t] += u;
        __syncthreads();
    }
    if (t < SCAN_BLOCKS) g_boff[t] = sm[t] - v;
}

__global__ void __launch_bounds__(1024) k_scan_c() {
    int i = blockIdx.x * 1024 + threadIdx.x;
    if (i < N_NODES) {
        int r = g_rowptr[i] + g_boff[blockIdx.x];
        g_rowptr[i] = r;
        g_cursor[i] = r;
        g_dinv[i] = rsqrtf((float)g_cnt[i] + 1.0f);
    }
    if (i == 0) g_rowptr[N_NODES] = E_EDGES;
}

__global__ void k_scatter(const int* __restrict__ ei) {
    int e4 = blockIdx.x * blockDim.x + threadIdx.x;
    if (e4 < E_EDGES / 4) {
        int4 s = ((const int4*)ei)[e4];
        int4 d = ((const int4*)(ei + E_EDGES))[e4];
        g_csr_src[atomicAdd(&g_cursor[d.x], 1)] = s.x;
        g_csr_src[atomicAdd(&g_cursor[d.y], 1)] = s.y;
        g_csr_src[atomicAdd(&g_cursor[d.z], 1)] = s.z;
        g_csr_src[atomicAdd(&g_cursor[d.w], 1)] = s.w;
    }
}

// ---------------------------------------------------------------------------
// W prep: fragment-packed. One thread per (layer, kc, n, tk).
// L1: bf16 main+res uint4. L2/L3: fp16 main-only uint2.
// ---------------------------------------------------------------------------
__global__ void k_wprep_all(const float* __restrict__ W1,
                            const float* __restrict__ W2,
                            const float* __restrict__ W3) {
    int t = blockIdx.x * 256 + threadIdx.x;
    if (t >= 3 * 8 * D * 4) return;
    int layer = t / (8 * D * 4);
    int idx   = t % (8 * D * 4);
    int kc = idx >> 9;
    int n  = (idx >> 2) & 127;
    int tk = idx & 3;
    int k0 = kc * 16 + tk * 2;
    int k1 = k0 + 8;

    const float* W = (layer == 0) ? W1 : (layer == 1) ? W2 : W3;
    float w00 = W[k0 * D + n],       w01 = W[(k0 + 1) * D + n];
    float w10 = W[k1 * D + n],       w11 = W[(k1 + 1) * D + n];

    if (layer == 0) {
        unsigned m0, r0, m1, r1;
        split2(make_float2(w00, w01), m0, r0);
        split2(make_float2(w10, w11), m1, r1);
        g_wpk1[idx] = make_uint4(m0, m1, r0, r1);
    } else {
        __half2 m0 = __floats2half2_rn(w00, w01);
        __half2 m1 = __floats2half2_rn(w10, w11);
        uint2 p = make_uint2(*(unsigned*)&m0, *(unsigned*)&m1);
        if (layer == 1) g_wpk2[idx] = p; else g_wpk3[idx] = p;
    }
}

// ---------------------------------------------------------------------------
// Layer-1 GEMM: bf16 split-compensated (A from fp32 x), 3 MMA terms.
// 8 warps; warp tile 32x64; block M=128, full N=128. Packed W fragments.
// ---------------------------------------------------------------------------
__global__ void __launch_bounds__(256)
k_gemm_l1(const float* __restrict__ X) {
    int tid  = threadIdx.x;
    int warp = tid >> 5, lane = tid & 31;
    int g  = lane >> 2;
    int tk = lane & 3;
    int m0 = blockIdx.x * 128 + (warp & 3) * 32;
    int n0 = (warp >> 2) * 64;

    float c[2][8][4];
#pragma unroll
    for (int t = 0; t < 2; ++t)
#pragma unroll
        for (int j = 0; j < 8; ++j)
#pragma unroll
            for (int q = 0; q < 4; ++q) c[t][j][q] = 0.0f;

#pragma unroll 1
    for (int kc = 0; kc < 8; ++kc) {
        int kb = kc * 16;

        unsigned am[2][4], ar[2][4];
#pragma unroll
        for (int t = 0; t < 2; ++t) {
            int r0 = m0 + t * 16 + g;
            int r1 = r0 + 8;
            float2 z = make_float2(0.f, 0.f);
            float2 x00 = (r0 < N_NODES) ? *(const float2*)&X[r0 * 128 + kb + tk * 2] : z;
            float2 x10 = (r1 < N_NODES) ? *(const float2*)&X[r1 * 128 + kb + tk * 2] : z;
            float2 x01 = (r0 < N_NODES) ? *(const float2*)&X[r0 * 128 + kb + 8 + tk * 2] : z;
            float2 x11 = (r1 < N_NODES) ? *(const float2*)&X[r1 * 128 + kb + 8 + tk * 2] : z;
            split2(x00, am[t][0], ar[t][0]);
            split2(x10, am[t][1], ar[t][1]);
            split2(x01, am[t][2], ar[t][2]);
            split2(x11, am[t][3], ar[t][3]);
        }

        unsigned bm[8][2], br[8][2];
#pragma unroll
        for (int j = 0; j < 8; ++j) {
            uint4 w = g_wpk1[((kc * 128 + n0 + j * 8 + g) << 2) + tk];
            bm[j][0] = w.x; bm[j][1] = w.y; br[j][0] = w.z; br[j][1] = w.w;
        }

#pragma unroll
        for (int t = 0; t < 2; ++t)
#pragma unroll
            for (int j = 0; j < 8; ++j) {
                mma_bf16(c[t][j], am[t][0], am[t][1], am[t][2], am[t][3],
                         bm[j][0], bm[j][1]);
                mma_bf16(c[t][j], ar[t][0], ar[t][1], ar[t][2], ar[t][3],
                         bm[j][0], bm[j][1]);
                mma_bf16(c[t][j], am[t][0], am[t][1], am[t][2], am[t][3],
                         br[j][0], br[j][1]);
            }
    }

#pragma unroll
    for (int t = 0; t < 2; ++t) {
        int r0 = m0 + t * 16 + g;
        int r1 = r0 + 8;
        float dv0 = (r0 < N_NODES) ? g_dinv[r0] : 0.f;
        float dv1 = (r1 < N_NODES) ? g_dinv[r1] : 0.f;
#pragma unroll
        for (int j = 0; j < 8; ++j) {
            int col = n0 + j * 8 + tk * 2;
            if (r0 < N_NODES)
                *(__half2*)&g_hh[r0 * 128 + col] =
                    __floats2half2_rn(dv0 * c[t][j][0], dv0 * c[t][j][1]);
            if (r1 < N_NODES)
                *(__half2*)&g_hh[r1 * 128 + col] =
                    __floats2half2_rn(dv1 * c[t][j][2], dv1 * c[t][j][3]);
        }
    }
}

// ---------------------------------------------------------------------------
// Layers 2/3 GEMM: A fp16-exact from permuted g_act, fp16 main-only W
// (uint2 packed), 1 MMA term per tile.
// ---------------------------------------------------------------------------
template <int LAYER>
__global__ void __launch_bounds__(256)
k_gemm_h() {
    const uint2* Wp = (LAYER == 2) ? g_wpk2 : g_wpk3;
    int tid  = threadIdx.x;
    int warp = tid >> 5, lane = tid & 31;
    int g  = lane >> 2;
    int tk = lane & 3;
    int m0 = blockIdx.x * 128 + (warp & 3) * 32;
    int n0 = (warp >> 2) * 64;

    const uint2* A = (const uint2*)g_act;   // permuted rows: uint2 idx r*32+kc*4+tk

    float c[2][8][4];
#pragma unroll
    for (int t = 0; t < 2; ++t)
#pragma unroll
        for (int j = 0; j < 8; ++j)
#pragma unroll
            for (int q = 0; q < 4; ++q) c[t][j][q] = 0.0f;

#pragma unroll 1
    for (int kc = 0; kc < 8; ++kc) {
        unsigned a[2][4];
#pragma unroll
        for (int t = 0; t < 2; ++t) {
            int r0 = m0 + t * 16 + g;
            int r1 = r0 + 8;
            uint2 z = make_uint2(0u, 0u);
            uint2 v0 = (r0 < N_NODES) ? A[r0 * 32 + kc * 4 + tk] : z;
            uint2 v1 = (r1 < N_NODES) ? A[r1 * 32 + kc * 4 + tk] : z;
            a[t][0] = v0.x; a[t][2] = v0.y;
            a[t][1] = v1.x; a[t][3] = v1.y;
        }

        unsigned bm[8][2];
#pragma unroll
        for (int j = 0; j < 8; ++j) {
            uint2 w = Wp[((kc * 128 + n0 + j * 8 + g) << 2) + tk];
            bm[j][0] = w.x; bm[j][1] = w.y;
        }

#pragma unroll
        for (int t = 0; t < 2; ++t)
#pragma unroll
            for (int j = 0; j < 8; ++j)
                mma_f16(c[t][j], a[t][0], a[t][1], a[t][2], a[t][3],
                        bm[j][0], bm[j][1]);
    }

#pragma unroll
    for (int t = 0; t < 2; ++t) {
        int r0 = m0 + t * 16 + g;
        int r1 = r0 + 8;
        float dv0 = (r0 < N_NODES) ? g_dinv[r0] : 0.f;
        float dv1 = (r1 < N_NODES) ? g_dinv[r1] : 0.f;
#pragma unroll
        for (int j = 0; j < 8; ++j) {
            int col = n0 + j * 8 + tk * 2;
            if (r0 < N_NODES)
                *(__half2*)&g_hh[r0 * 128 + col] =
                    __floats2half2_rn(dv0 * c[t][j][0], dv0 * c[t][j][1]);
            if (r1 < N_NODES)
                *(__half2*)&g_hh[r1 * 128 + col] =
                    __floats2half2_rn(dv1 * c[t][j][2], dv1 * c[t][j][3]);
        }
    }
}

// ---------------------------------------------------------------------------
// Aggregation: 16 lanes per dst node; lane owns 8 halves (uint4) of the row.
// out = relu( dinv[dst] * ( sum_src H'[src] + H'[dst] ) + b ).
// TO_OUT=false -> writes g_act in FRAGMENT-PERMUTED order (4 STG.32).
// ---------------------------------------------------------------------------
template <bool TO_OUT>
__global__ void __launch_bounds__(256)
k_agg(const float* __restrict__ b, float* __restrict__ OUT) {
    int node = blockIdx.x * 16 + (threadIdx.x >> 4);
    int lane16 = threadIdx.x & 15;
    if (node >= N_NODES) return;

    const uint4* Hv = (const uint4*)g_hh;

    float dv = g_dinv[node];
    float acc[8];
    {
        uint4 raw = Hv[node * 16 + lane16];
        float2 q0 = __half22float2(*(__half2*)&raw.x);
        float2 q1 = __half22float2(*(__half2*)&raw.y);
        float2 q2 = __half22float2(*(__half2*)&raw.z);
        float2 q3 = __half22float2(*(__half2*)&raw.w);
        acc[0] = q0.x; acc[1] = q0.y; acc[2] = q1.x; acc[3] = q1.y;
        acc[4] = q2.x; acc[5] = q2.y; acc[6] = q3.x; acc[7] = q3.y;
    }

    int j = g_rowptr[node];
    int end = g_rowptr[node + 1];

    while (j < end) {
        int take = end - j;
        if (take > 16) take = 16;
        int sidx = (lane16 < take) ? g_csr_src[j + lane16] : 0;
#pragma unroll 4
        for (int t = 0; t < take; ++t) {
            int s = __shfl_sync(0xffffffffu, sidx, t, 16);
            uint4 raw = Hv[s * 16 + lane16];
            float2 q0 = __half22float2(*(__half2*)&raw.x);
            float2 q1 = __half22float2(*(__half2*)&raw.y);
            float2 q2 = __half22float2(*(__half2*)&raw.z);
            float2 q3 = __half22float2(*(__half2*)&raw.w);
            acc[0] += q0.x; acc[1] += q0.y; acc[2] += q1.x; acc[3] += q1.y;
            acc[4] += q2.x; acc[5] += q2.y; acc[6] += q3.x; acc[7] += q3.y;
        }
        j += take;
    }

    float4 bb0 = *(const float4*)&b[lane16 * 8];
    float4 bb1 = *(const float4*)&b[lane16 * 8 + 4];
    float o[8];
    o[0] = fmaxf(fmaf(dv, acc[0], bb0.x), 0.f);
    o[1] = fmaxf(fmaf(dv, acc[1], bb0.y), 0.f);
    o[2] = fmaxf(fmaf(dv, acc[2], bb0.z), 0.f);
    o[3] = fmaxf(fmaf(dv, acc[3], bb0.w), 0.f);
    o[4] = fmaxf(fmaf(dv, acc[4], bb1.x), 0.f);
    o[5] = fmaxf(fmaf(dv, acc[5], bb1.y), 0.f);
    o[6] = fmaxf(fmaf(dv, acc[6], bb1.z), 0.f);
    o[7] = fmaxf(fmaf(dv, acc[7], bb1.w), 0.f);

    if (TO_OUT) {
        ((float4*)OUT)[node * 32 + lane16 * 2]     = make_float4(o[0], o[1], o[2], o[3]);
        ((float4*)OUT)[node * 32 + lane16 * 2 + 1] = make_float4(o[4], o[5], o[6], o[7]);
    } else {
        int cch = lane16 >> 1;
        int odd = lane16 & 1;
        unsigned* dst = (unsigned*)g_act + node * 64 + cch * 8 + odd;
        __half2 h0 = __floats2half2_rn(o[0], o[1]);
        __half2 h1 = __floats2half2_rn(o[2], o[3]);
        __half2 h2 = __floats2half2_rn(o[4], o[5]);
        __half2 h3 = __floats2half2_rn(o[6], o[7]);
        dst[0] = *(unsigned*)&h0;
        dst[2] = *(unsigned*)&h1;
        dst[4] = *(unsigned*)&h2;
        dst[6] = *(unsigned*)&h3;
    }
}

// ---------------------------------------------------------------------------
extern "C" void kernel_launch(void* const* d_in, const int* in_sizes, int n_in,
                              void* d_out, int out_size) {
    const float* x  = (const float*)d_in[0];
    const int*   ei = (const int*)d_in[1];
    const float* W1 = (const float*)d_in[2];
    const float* b1 = (const float*)d_in[3];
    const float* W2 = (const float*)d_in[4];
    const float* b2 = (const float*)d_in[5];
    const float* W3 = (const float*)d_in[6];
    const float* b3 = (const float*)d_in[7];
    float* out = (float*)d_out;

    // W prep for all layers (single launch)
    k_wprep_all<<<(3 * 8 * D * 4 + 255) / 256, 256>>>(W1, W2, W3);

    // CSR build (dinv needed by GEMM epilogue)
    k_zero_cnt<<<(N_NODES + 255) / 256, 256>>>();
    k_count<<<(E_EDGES / 4 + 255) / 256, 256>>>(ei);
    k_scan_a<<<SCAN_BLOCKS, 1024>>>();
    k_scan_b<<<1, 128>>>();
    k_scan_c<<<SCAN_BLOCKS, 1024>>>();
    k_scatter<<<(E_EDGES / 4 + 255) / 256, 256>>>(ei);

    const int gemm_blocks = (N_NODES + 127) / 128;          // 782
    const int agg_blocks  = (N_NODES + 15) / 16;            // 6250

    // Layer 1: x -> g_hh -> g_act (permuted)
    k_gemm_l1<<<gemm_blocks, 256>>>(x);
    k_agg<false><<<agg_blocks, 256>>>(b1, nullptr);
    // Layer 2: g_act -> g_hh -> g_act
    k_gemm_h<2><<<gemm_blocks, 256>>>();
    k_agg<false><<<agg_blocks, 256>>>(b2, nullptr);
    // Layer 3: g_act -> g_hh -> out (fp32, unpermuted)
    k_gemm_h<3><<<gemm_blocks, 256>>>();
    k_agg<true><<<agg_blocks, 256>>>(b3, out);
}

// round 13
// speedup vs baseline: 2.8108x; 1.0670x over previous
#include <cuda_runtime.h>
#include <cuda_bf16.h>
#include <cuda_fp16.h>

#define N_NODES 100000
#define D 128
#define E_EDGES 1600000
#define SCAN_BLOCKS ((N_NODES + 1023) / 1024)   // 98

// Scratch (device globals; no runtime allocation allowed)
__device__ __half g_hh[N_NODES * D];   // pre-normalized messages dinv*H, fp16
__device__ __half g_act[N_NODES * D];  // activations, fp16, FRAGMENT-PERMUTED rows
__device__ float g_dinv[N_NODES];
__device__ int   g_cnt[N_NODES];
__device__ int   g_rowptr[N_NODES + 1];
__device__ int   g_cursor[N_NODES];
__device__ int   g_csr_src[E_EDGES];
__device__ int   g_bsum[SCAN_BLOCKS];
__device__ int   g_boff[SCAN_BLOCKS];
// Fragment-packed W (fp16 main only): [kc][n][tk] -> {bm0,bm1}
__device__ uint2 g_wpk1[8 * D * 4];
__device__ uint2 g_wpk2[8 * D * 4];
__device__ uint2 g_wpk3[8 * D * 4];

// Side stream + events for fork-join graph capture (host driver objects,
// created once at program load — no device memory allocation).
struct SideRes {
    cudaStream_t s;
    cudaEvent_t fork, dinv, csr;
    SideRes() {
        cudaStreamCreateWithFlags(&s, cudaStreamNonBlocking);
        cudaEventCreateWithFlags(&fork, cudaEventDisableTiming);
        cudaEventCreateWithFlags(&dinv, cudaEventDisableTiming);
        cudaEventCreateWithFlags(&csr,  cudaEventDisableTiming);
    }
};
static SideRes g_res;

// ---------------------------------------------------------------------------
// Helpers
// ---------------------------------------------------------------------------
__device__ __forceinline__ void split2h(float2 v, unsigned& m, unsigned& r) {
    __half2 hm = __floats2half2_rn(v.x, v.y);
    float2 back = __half22float2(hm);
    __half2 hr = __floats2half2_rn(v.x - back.x, v.y - back.y);
    m = *(unsigned*)&hm;
    r = *(unsigned*)&hr;
}

__device__ __forceinline__ void mma_f16(float* c, unsigned a0, unsigned a1,
                                        unsigned a2, unsigned a3,
                                        unsigned b0, unsigned b1) {
    asm volatile(
        "mma.sync.aligned.m16n8k16.row.col.f32.f16.f16.f32 "
        "{%0,%1,%2,%3}, {%4,%5,%6,%7}, {%8,%9}, {%0,%1,%2,%3};"
        : "+f"(c[0]), "+f"(c[1]), "+f"(c[2]), "+f"(c[3])
        : "r"(a0), "r"(a1), "r"(a2), "r"(a3), "r"(b0), "r"(b1));
}

// ---------------------------------------------------------------------------
// CSR build: histogram -> dinv -> parallel scan -> scatter (4 edges/thread)
// ---------------------------------------------------------------------------
__global__ void k_zero_cnt() {
    int i = blockIdx.x * blockDim.x + threadIdx.x;
    if (i < N_NODES) g_cnt[i] = 0;
}

__global__ void k_count(const int* __restrict__ ei) {
    int e4 = blockIdx.x * blockDim.x + threadIdx.x;
    if (e4 < E_EDGES / 4) {
        int4 d = ((const int4*)(ei + E_EDGES))[e4];
        atomicAdd(&g_cnt[d.x], 1);
        atomicAdd(&g_cnt[d.y], 1);
        atomicAdd(&g_cnt[d.z], 1);
        atomicAdd(&g_cnt[d.w], 1);
    }
}

__global__ void k_dinv() {
    int i = blockIdx.x * blockDim.x + threadIdx.x;
    if (i < N_NODES) g_dinv[i] = rsqrtf((float)g_cnt[i] + 1.0f);
}

__global__ void __launch_bounds__(1024) k_scan_a() {
    __shared__ int sm[1024];
    int t = threadIdx.x;
    int i = blockIdx.x * 1024 + t;
    int v = (i < N_NODES) ? g_cnt[i] : 0;
    sm[t] = v;
    __syncthreads();
#pragma unroll
    for (int off = 1; off < 1024; off <<= 1) {
        int u = (t >= off) ? sm[t - off] : 0;
        __syncthreads();
        sm[t] += u;
        __syncthreads();
    }
    if (i < N_NODES) g_rowptr[i] = sm[t] - v;
    if (t == 1023) g_bsum[blockIdx.x] = sm[1023];
}

__global__ void __launch_bounds__(128) k_scan_b() {
    __shared__ int sm[128];
    int t = threadIdx.x;
    int v = (t < SCAN_BLOCKS) ? g_bsum[t] : 0;
    sm[t] = v;
    __syncthreads();
#pragma unroll
    for (int off = 1; off < 128; off <<= 1) {
        int u = (t >= off) ? sm[t - off] : 0;
        __syncthreads();
        sm[t] += u;
        __syncthreads();
    }
    if (t < SCAN_BLOCKS) g_boff[t] = sm[t] - v;
}

__global__ void __launch_bounds__(1024) k_scan_c() {
    int i = blockIdx.x * 1024 + threadIdx.x;
    if (i < N_NODES) {
        int r = g_rowptr[i] + g_boff[blockIdx.x];
        g_rowptr[i] = r;
        g_cursor[i] = r;
    }
    if (i == 0) g_rowptr[N_NODES] = E_EDGES;
}

__global__ void k_scatter(const int* __restrict__ ei) {
    int e4 = blockIdx.x * blockDim.x + threadIdx.x;
    if (e4 < E_EDGES / 4) {
        int4 s = ((const int4*)ei)[e4];
        int4 d = ((const int4*)(ei + E_EDGES))[e4];
        g_csr_src[atomicAdd(&g_cursor[d.x], 1)] = s.x;
        g_csr_src[atomicAdd(&g_cursor[d.y], 1)] = s.y;
        g_csr_src[atomicAdd(&g_cursor[d.z], 1)] = s.z;
        g_csr_src[atomicAdd(&g_cursor[d.w], 1)] = s.w;
    }
}

// ---------------------------------------------------------------------------
// W prep: fp16 main-only, fragment-packed uint2 {bm0,bm1}, all 3 layers.
// ---------------------------------------------------------------------------
__global__ void k_wprep_all(const float* __restrict__ W1,
                            const float* __restrict__ W2,
                            const float* __restrict__ W3) {
    int t = blockIdx.x * 256 + threadIdx.x;
    if (t >= 3 * 8 * D * 4) return;
    int layer = t / (8 * D * 4);
    int idx   = t % (8 * D * 4);
    int kc = idx >> 9;
    int n  = (idx >> 2) & 127;
    int tk = idx & 3;
    int k0 = kc * 16 + tk * 2;
    int k1 = k0 + 8;

    const float* W = (layer == 0) ? W1 : (layer == 1) ? W2 : W3;
    __half2 m0 = __floats2half2_rn(W[k0 * D + n], W[(k0 + 1) * D + n]);
    __half2 m1 = __floats2half2_rn(W[k1 * D + n], W[(k1 + 1) * D + n]);
    uint2 p = make_uint2(*(unsigned*)&m0, *(unsigned*)&m1);
    if (layer == 0) g_wpk1[idx] = p;
    else if (layer == 1) g_wpk2[idx] = p;
    else g_wpk3[idx] = p;
}

// ---------------------------------------------------------------------------
// Layer-1 GEMM: A = fp16 main+residual of fp32 x (2 MMA terms), W fp16 main.
// 8 warps; warp tile 32x64; block M=128, full N=128.
// Epilogue stores dinv[m]*(x@W) as fp16 into g_hh.
// ---------------------------------------------------------------------------
__global__ void __launch_bounds__(256)
k_gemm_l1(const float* __restrict__ X) {
    int tid  = threadIdx.x;
    int warp = tid >> 5, lane = tid & 31;
    int g  = lane >> 2;
    int tk = lane & 3;
    int m0 = blockIdx.x * 128 + (warp & 3) * 32;
    int n0 = (warp >> 2) * 64;

    float c[2][8][4];
#pragma unroll
    for (int t = 0; t < 2; ++t)
#pragma unroll
        for (int j = 0; j < 8; ++j)
#pragma unroll
            for (int q = 0; q < 4; ++q) c[t][j][q] = 0.0f;

#pragma unroll 1
    for (int kc = 0; kc < 8; ++kc) {
        int kb = kc * 16;

        unsigned am[2][4], ar[2][4];
#pragma unroll
        for (int t = 0; t < 2; ++t) {
            int r0 = m0 + t * 16 + g;
            int r1 = r0 + 8;
            float2 z = make_float2(0.f, 0.f);
            float2 x00 = (r0 < N_NODES) ? *(const float2*)&X[r0 * 128 + kb + tk * 2] : z;
            float2 x10 = (r1 < N_NODES) ? *(const float2*)&X[r1 * 128 + kb + tk * 2] : z;
            float2 x01 = (r0 < N_NODES) ? *(const float2*)&X[r0 * 128 + kb + 8 + tk * 2] : z;
            float2 x11 = (r1 < N_NODES) ? *(const float2*)&X[r1 * 128 + kb + 8 + tk * 2] : z;
            split2h(x00, am[t][0], ar[t][0]);
            split2h(x10, am[t][1], ar[t][1]);
            split2h(x01, am[t][2], ar[t][2]);
            split2h(x11, am[t][3], ar[t][3]);
        }

        unsigned bm[8][2];
#pragma unroll
        for (int j = 0; j < 8; ++j) {
            uint2 w = g_wpk1[((kc * 128 + n0 + j * 8 + g) << 2) + tk];
            bm[j][0] = w.x; bm[j][1] = w.y;
        }

#pragma unroll
        for (int t = 0; t < 2; ++t)
#pragma unroll
            for (int j = 0; j < 8; ++j) {
                mma_f16(c[t][j], am[t][0], am[t][1], am[t][2], am[t][3],
                        bm[j][0], bm[j][1]);
                mma_f16(c[t][j], ar[t][0], ar[t][1], ar[t][2], ar[t][3],
                        bm[j][0], bm[j][1]);
            }
    }

#pragma unroll
    for (int t = 0; t < 2; ++t) {
        int r0 = m0 + t * 16 + g;
        int r1 = r0 + 8;
        float dv0 = (r0 < N_NODES) ? g_dinv[r0] : 0.f;
        float dv1 = (r1 < N_NODES) ? g_dinv[r1] : 0.f;
#pragma unroll
        for (int j = 0; j < 8; ++j) {
            int col = n0 + j * 8 + tk * 2;
            if (r0 < N_NODES)
                *(__half2*)&g_hh[r0 * 128 + col] =
                    __floats2half2_rn(dv0 * c[t][j][0], dv0 * c[t][j][1]);
            if (r1 < N_NODES)
                *(__half2*)&g_hh[r1 * 128 + col] =
                    __floats2half2_rn(dv1 * c[t][j][2], dv1 * c[t][j][3]);
        }
    }
}

// ---------------------------------------------------------------------------
// Layers 2/3 GEMM: A fp16-exact from permuted g_act, fp16 main-only W.
// ---------------------------------------------------------------------------
template <int LAYER>
__global__ void __launch_bounds__(256)
k_gemm_h() {
    const uint2* Wp = (LAYER == 2) ? g_wpk2 : g_wpk3;
    int tid  = threadIdx.x;
    int warp = tid >> 5, lane = tid & 31;
    int g  = lane >> 2;
    int tk = lane & 3;
    int m0 = blockIdx.x * 128 + (warp & 3) * 32;
    int n0 = (warp >> 2) * 64;

    const uint2* A = (const uint2*)g_act;   // permuted rows: uint2 idx r*32+kc*4+tk

    float c[2][8][4];
#pragma unroll
    for (int t = 0; t < 2; ++t)
#pragma unroll
        for (int j = 0; j < 8; ++j)
#pragma unroll
            for (int q = 0; q < 4; ++q) c[t][j][q] = 0.0f;

#pragma unroll 1
    for (int kc = 0; kc < 8; ++kc) {
        unsigned a[2][4];
#pragma unroll
        for (int t = 0; t < 2; ++t) {
            int r0 = m0 + t * 16 + g;
            int r1 = r0 + 8;
            uint2 z = make_uint2(0u, 0u);
            uint2 v0 = (r0 < N_NODES) ? A[r0 * 32 + kc * 4 + tk] : z;
            uint2 v1 = (r1 < N_NODES) ? A[r1 * 32 + kc * 4 + tk] : z;
            a[t][0] = v0.x; a[t][2] = v0.y;
            a[t][1] = v1.x; a[t][3] = v1.y;
        }

        unsigned bm[8][2];
#pragma unroll
        for (int j = 0; j < 8; ++j) {
            uint2 w = Wp[((kc * 128 + n0 + j * 8 + g) << 2) + tk];
            bm[j][0] = w.x; bm[j][1] = w.y;
        }

#pragma unroll
        for (int t = 0; t < 2; ++t)
#pragma unroll
            for (int j = 0; j < 8; ++j)
                mma_f16(c[t][j], a[t][0], a[t][1], a[t][2], a[t][3],
                        bm[j][0], bm[j][1]);
    }

#pragma unroll
    for (int t = 0; t < 2; ++t) {
        int r0 = m0 + t * 16 + g;
        int r1 = r0 + 8;
        float dv0 = (r0 < N_NODES) ? g_dinv[r0] : 0.f;
        float dv1 = (r1 < N_NODES) ? g_dinv[r1] : 0.f;
#pragma unroll
        for (int j = 0; j < 8; ++j) {
            int col = n0 + j * 8 + tk * 2;
            if (r0 < N_NODES)
                *(__half2*)&g_hh[r0 * 128 + col] =
                    __floats2half2_rn(dv0 * c[t][j][0], dv0 * c[t][j][1]);
            if (r1 < N_NODES)
                *(__half2*)&g_hh[r1 * 128 + col] =
                    __floats2half2_rn(dv1 * c[t][j][2], dv1 * c[t][j][3]);
        }
    }
}

// ---------------------------------------------------------------------------
// Aggregation: 16 lanes per dst node; lane owns 8 halves (uint4) of the row.
// out = relu( dinv[dst] * ( sum_src H'[src] + H'[dst] ) + b ).
// TO_OUT=false -> writes g_act in FRAGMENT-PERMUTED order.
// ---------------------------------------------------------------------------
template <bool TO_OUT>
__global__ void __launch_bounds__(256)
k_agg(const float* __restrict__ b, float* __restrict__ OUT) {
    int node = blockIdx.x * 16 + (threadIdx.x >> 4);
    int lane16 = threadIdx.x & 15;
    if (node >= N_NODES) return;

    const uint4* Hv = (const uint4*)g_hh;

    float dv = g_dinv[node];
    float acc[8];
    {
        uint4 raw = Hv[node * 16 + lane16];
        float2 q0 = __half22float2(*(__half2*)&raw.x);
        float2 q1 = __half22float2(*(__half2*)&raw.y);
        float2 q2 = __half22float2(*(__half2*)&raw.z);
        float2 q3 = __half22float2(*(__half2*)&raw.w);
        acc[0] = q0.x; acc[1] = q0.y; acc[2] = q1.x; acc[3] = q1.y;
        acc[4] = q2.x; acc[5] = q2.y; acc[6] = q3.x; acc[7] = q3.y;
    }

    int j = g_rowptr[node];
    int end = g_rowptr[node + 1];

    while (j < end) {
        int take = end - j;
        if (take > 16) take = 16;
        int sidx = (lane16 < take) ? g_csr_src[j + lane16] : 0;
#pragma unroll 4
        for (int t = 0; t < take; ++t) {
            int s = __shfl_sync(0xffffffffu, sidx, t, 16);
            uint4 raw = Hv[s * 16 + lane16];
            float2 q0 = __half22float2(*(__half2*)&raw.x);
            float2 q1 = __half22float2(*(__half2*)&raw.y);
            float2 q2 = __half22float2(*(__half2*)&raw.z);
            float2 q3 = __half22float2(*(__half2*)&raw.w);
            acc[0] += q0.x; acc[1] += q0.y; acc[2] += q1.x; acc[3] += q1.y;
            acc[4] += q2.x; acc[5] += q2.y; acc[6] += q3.x; acc[7] += q3.y;
        }
        j += take;
    }

    float4 bb0 = *(const float4*)&b[lane16 * 8];
    float4 bb1 = *(const float4*)&b[lane16 * 8 + 4];
    float o[8];
    o[0] = fmaxf(fmaf(dv, acc[0], bb0.x), 0.f);
    o[1] = fmaxf(fmaf(dv, acc[1], bb0.y), 0.f);
    o[2] = fmaxf(fmaf(dv, acc[2], bb0.z), 0.f);
    o[3] = fmaxf(fmaf(dv, acc[3], bb0.w), 0.f);
    o[4] = fmaxf(fmaf(dv, acc[4], bb1.x), 0.f);
    o[5] = fmaxf(fmaf(dv, acc[5], bb1.y), 0.f);
    o[6] = fmaxf(fmaf(dv, acc[6], bb1.z), 0.f);
    o[7] = fmaxf(fmaf(dv, acc[7], bb1.w), 0.f);

    if (TO_OUT) {
        ((float4*)OUT)[node * 32 + lane16 * 2]     = make_float4(o[0], o[1], o[2], o[3]);
        ((float4*)OUT)[node * 32 + lane16 * 2 + 1] = make_float4(o[4], o[5], o[6], o[7]);
    } else {
        int cch = lane16 >> 1;
        int odd = lane16 & 1;
        unsigned* dst = (unsigned*)g_act + node * 64 + cch * 8 + odd;
        __half2 h0 = __floats2half2_rn(o[0], o[1]);
        __half2 h1 = __floats2half2_rn(o[2], o[3]);
        __half2 h2 = __floats2half2_rn(o[4], o[5]);
        __half2 h3 = __floats2half2_rn(o[6], o[7]);
        dst[0] = *(unsigned*)&h0;
        dst[2] = *(unsigned*)&h1;
        dst[4] = *(unsigned*)&h2;
        dst[6] = *(unsigned*)&h3;
    }
}

// ---------------------------------------------------------------------------
extern "C" void kernel_launch(void* const* d_in, const int* in_sizes, int n_in,
                              void* d_out, int out_size) {
    const float* x  = (const float*)d_in[0];
    const int*   ei = (const int*)d_in[1];
    const float* W1 = (const float*)d_in[2];
    const float* b1 = (const float*)d_in[3];
    const float* W2 = (const float*)d_in[4];
    const float* b2 = (const float*)d_in[5];
    const float* W3 = (const float*)d_in[6];
    const float* b3 = (const float*)d_in[7];
    float* out = (float*)d_out;

    cudaStream_t side = g_res.s;

    // Fork: side stream builds CSR (+dinv early), main does wprep + gemm_l1.
    cudaEventRecord(g_res.fork, 0);
    cudaStreamWaitEvent(side, g_res.fork, 0);

    // Side: degree histogram -> dinv -> scan -> scatter
    k_zero_cnt<<<(N_NODES + 255) / 256, 256, 0, side>>>();
    k_count<<<(E_EDGES / 4 + 255) / 256, 256, 0, side>>>(ei);
    k_dinv<<<(N_NODES + 255) / 256, 256, 0, side>>>();
    cudaEventRecord(g_res.dinv, side);
    k_scan_a<<<SCAN_BLOCKS, 1024, 0, side>>>();
    k_scan_b<<<1, 128, 0, side>>>();
    k_scan_c<<<SCAN_BLOCKS, 1024, 0, side>>>();
    k_scatter<<<(E_EDGES / 4 + 255) / 256, 256, 0, side>>>(ei);
    cudaEventRecord(g_res.csr, side);

    const int gemm_blocks = (N_NODES + 127) / 128;          // 782
    const int agg_blocks  = (N_NODES + 15) / 16;            // 6250

    // Main: W prep (independent), then gemm_l1 (needs dinv only)
    k_wprep_all<<<(3 * 8 * D * 4 + 255) / 256, 256>>>(W1, W2, W3);
    cudaStreamWaitEvent(0, g_res.dinv, 0);
    k_gemm_l1<<<gemm_blocks, 256>>>(x);
    cudaStreamWaitEvent(0, g_res.csr, 0);   // join: agg needs rowptr/csr_src

    // Layer 1: -> g_act (permuted)
    k_agg<false><<<agg_blocks, 256>>>(b1, nullptr);
    // Layer 2
    k_gemm_h<2><<<gemm_blocks, 256>>>();
    k_agg<false><<<agg_blocks, 256>>>(b2, nullptr);
    // Layer 3
    k_gemm_h<3><<<gemm_blocks, 256>>>();
    k_agg<true><<<agg_blocks, 256>>>(b3, out);
}